// round 11
// baseline (speedup 1.0000x reference)
#include <cuda_runtime.h>
#include <cuda_bf16.h>
#include <math.h>
#include <stdint.h>

#define NN 100000
#define EE 1250000
#define DD 64
#define HH 256
#define CC 40
#define BNEPS 1e-5f

#define NCTA 592
#define NTHR 256
#define CHUNK 169   // ceil(100000/592)

// ---------------- device scratch ----------------
__device__ float g_z1[NN * DD];
__device__ float g_z2[NN * DD];
__device__ float g_z3[NN * DD];
__device__ float g_z4[NN * DD];
__device__ float g_norm[NN];
__device__ float g_sdeg[NN];
__device__ int   g_deg[NN];       // zero at load; re-zeroed each call (phase E)
__device__ int   g_off[NN + 1];
__device__ int   g_cursor[NN];
__device__ int   g_csr[EE];
__device__ int   g_part[NCTA];
__device__ float g_y1[NN * HH];
__device__ float g_y2[NN * HH];
__device__ float g_stats[4 * HH]; // zero at load; re-zeroed each call (phase E)
__device__ __nv_bfloat16 g_w1h[HH * DD], g_w1l[HH * DD];
__device__ __nv_bfloat16 g_w2h[HH * HH], g_w2l[HH * HH];
__device__ __nv_bfloat16 g_w3h[64 * HH], g_w3l[64 * HH];
// global barrier state
__device__ int g_barCount;
__device__ volatile int g_barGen;

// ---------------- helpers ----------------
__device__ __forceinline__ uint32_t smem_u32(const void* p) {
    uint32_t a;
    asm("{ .reg .u64 t; cvta.to.shared.u64 t, %1; cvt.u32.u64 %0, t; }" : "=r"(a) : "l"(p));
    return a;
}
__device__ __forceinline__ void ldm_x4(uint32_t* r, uint32_t addr) {
    asm volatile("ldmatrix.sync.aligned.m8n8.x4.shared.b16 {%0,%1,%2,%3}, [%4];"
                 : "=r"(r[0]), "=r"(r[1]), "=r"(r[2]), "=r"(r[3]) : "r"(addr));
}
__device__ __forceinline__ void mma_bf16(float* c, const uint32_t* a, const uint32_t* b) {
    asm volatile(
        "mma.sync.aligned.m16n8k16.row.col.f32.bf16.bf16.f32 "
        "{%0,%1,%2,%3}, {%4,%5,%6,%7}, {%8,%9}, {%0,%1,%2,%3};"
        : "+f"(c[0]), "+f"(c[1]), "+f"(c[2]), "+f"(c[3])
        : "r"(a[0]), "r"(a[1]), "r"(a[2]), "r"(a[3]), "r"(b[0]), "r"(b[1]));
}
__device__ __forceinline__ void split_pack(float x, float y, uint32_t& hi, uint32_t& lo) {
    uint32_t h;
    asm("cvt.rn.bf16x2.f32 %0, %1, %2;" : "=r"(h) : "f"(y), "f"(x));
    float xb = __uint_as_float(h << 16);
    float yb = __uint_as_float(h & 0xffff0000u);
    float rx = x - xb, ry = y - yb;
    uint32_t l;
    asm("cvt.rn.bf16x2.f32 %0, %1, %2;" : "=r"(l) : "f"(ry), "f"(rx));
    hi = h;
    lo = l;
}
__device__ __forceinline__ void wsplit(const float* W, __nv_bfloat16* hi, __nv_bfloat16* lo,
                                       int idx, int K, int Nsrc) {
    int n = idx / K, k = idx - n * K;
    float v = (n < Nsrc) ? W[(size_t)k * Nsrc + n] : 0.0f;
    __nv_bfloat16 h = __float2bfloat16(v);
    hi[idx] = h;
    lo[idx] = __float2bfloat16(v - __bfloat162float(h));
}

// sense-reversing global barrier (all NCTA CTAs resident)
__device__ __forceinline__ void gbar() {
    __syncthreads();
    if (threadIdx.x == 0) {
        __threadfence();
        int gen = g_barGen;
        if (atomicAdd(&g_barCount, 1) == NCTA - 1) {
            g_barCount = 0;
            __threadfence();
            g_barGen = gen + 1;
        } else {
            while (g_barGen == gen) { }
        }
        __threadfence();
    }
    __syncthreads();
}

// one gather round over all nodes (persistent-warp form)
__device__ void gather_round(const float* __restrict__ zin, float* __restrict__ zout,
                             int first, int gwarp, int totalWarps, int lane) {
    int grp = lane >> 4, sub = lane & 15;
    const float4* z4 = (const float4*)zin;
    for (int node = gwarp; node < NN; node += totalWarps) {
        int beg = g_off[node], end = g_off[node + 1];
        float4 a = make_float4(0.f, 0.f, 0.f, 0.f);
        float4 b = make_float4(0.f, 0.f, 0.f, 0.f);
        int e = beg + grp;
        for (; e + 2 < end; e += 4) {
            int j0 = g_csr[e], j1 = g_csr[e + 2];
            float4 v0 = z4[j0 * 16 + sub];
            float4 v1 = z4[j1 * 16 + sub];
            if (first) {
                float n0 = g_norm[j0], n1 = g_norm[j1];
                a.x = fmaf(n0, v0.x, a.x); a.y = fmaf(n0, v0.y, a.y);
                a.z = fmaf(n0, v0.z, a.z); a.w = fmaf(n0, v0.w, a.w);
                b.x = fmaf(n1, v1.x, b.x); b.y = fmaf(n1, v1.y, b.y);
                b.z = fmaf(n1, v1.z, b.z); b.w = fmaf(n1, v1.w, b.w);
            } else {
                a.x += v0.x; a.y += v0.y; a.z += v0.z; a.w += v0.w;
                b.x += v1.x; b.y += v1.y; b.z += v1.z; b.w += v1.w;
            }
        }
        if (e < end) {
            int j = g_csr[e];
            float4 v = z4[j * 16 + sub];
            if (first) {
                float nj = g_norm[j];
                a.x = fmaf(nj, v.x, a.x); a.y = fmaf(nj, v.y, a.y);
                a.z = fmaf(nj, v.z, a.z); a.w = fmaf(nj, v.w, a.w);
            } else {
                a.x += v.x; a.y += v.y; a.z += v.z; a.w += v.w;
            }
        }
        a.x += b.x; a.y += b.y; a.z += b.z; a.w += b.w;
        a.x += __shfl_xor_sync(0xffffffffu, a.x, 16);
        a.y += __shfl_xor_sync(0xffffffffu, a.y, 16);
        a.z += __shfl_xor_sync(0xffffffffu, a.z, 16);
        a.w += __shfl_xor_sync(0xffffffffu, a.w, 16);
        if (grp == 0) {
            float ni = g_norm[node];
            float n2 = ni * ni;
            ((float4*)zout)[node * 16 + sub] =
                make_float4(n2 * a.x, n2 * a.y, n2 * a.z, n2 * a.w);
        }
    }
}

// ---------------- persistent mega kernel: CSR build + 4 gather rounds --------
__global__ __launch_bounds__(NTHR, 4) void k_mega(
    const int* __restrict__ src, const int* __restrict__ dst,
    const float* __restrict__ feat,
    const float* __restrict__ W1, const float* __restrict__ W2,
    const float* __restrict__ W3)
{
    __shared__ int sm[NTHR];
    __shared__ int smx[1024];

    int t = threadIdx.x;
    int gtid = blockIdx.x * NTHR + t;
    const int T = NCTA * NTHR;                 // 151552
    int lane = t & 31;
    int gwarp = gtid >> 5;
    const int totalWarps = T / 32;             // 4736

    // ---- phase A: degree count + weight split ----
    for (int e = gtid; e < EE; e += T)
        atomicAdd(&g_deg[dst[e]], 1);
    {
        const int W1N = HH * DD, W2N = HH * HH, W3N = 64 * HH;
        for (int i = gtid; i < W1N + W2N + W3N; i += T) {
            if (i < W1N) wsplit(W1, g_w1h, g_w1l, i, DD, HH);
            else if (i < W1N + W2N) wsplit(W2, g_w2h, g_w2l, i - W1N, HH, HH);
            else wsplit(W3, g_w3h, g_w3l, i - W1N - W2N, HH, CC);
        }
    }
    gbar();

    // ---- phase B: per-CTA degree partial sum ----
    {
        int base0 = blockIdx.x * CHUNK;
        int cnt = NN - base0; if (cnt > CHUNK) cnt = CHUNK;
        int v = (t < cnt && cnt > 0) ? g_deg[base0 + t] : 0;
        sm[t] = v;
        __syncthreads();
        for (int off = 1; off < NTHR; off <<= 1) {
            int x = (t >= off) ? sm[t - off] : 0;
            __syncthreads();
            sm[t] += x;
            __syncthreads();
        }
        if (t == NTHR - 1) g_part[blockIdx.x] = sm[NTHR - 1];
    }
    gbar();

    // ---- phase C: CTA 0 scans 592 partials -> exclusive prefix ----
    if (blockIdx.x == 0) {
        // thread t owns elements [4t, 4t+4)
        int v0 = 0, v1 = 0, v2 = 0, v3 = 0;
        int b0 = t * 4;
        if (b0 + 0 < NCTA) v0 = g_part[b0 + 0];
        if (b0 + 1 < NCTA) v1 = g_part[b0 + 1];
        if (b0 + 2 < NCTA) v2 = g_part[b0 + 2];
        if (b0 + 3 < NCTA) v3 = g_part[b0 + 3];
        int tsum = v0 + v1 + v2 + v3;
        sm[t] = tsum;
        __syncthreads();
        for (int off = 1; off < NTHR; off <<= 1) {
            int x = (t >= off) ? sm[t - off] : 0;
            __syncthreads();
            sm[t] += x;
            __syncthreads();
        }
        int texcl = sm[t] - tsum;
        if (b0 + 0 < NCTA) g_part[b0 + 0] = texcl;
        if (b0 + 1 < NCTA) g_part[b0 + 1] = texcl + v0;
        if (b0 + 2 < NCTA) g_part[b0 + 2] = texcl + v0 + v1;
        if (b0 + 3 < NCTA) g_part[b0 + 3] = texcl + v0 + v1 + v2;
    }
    gbar();

    // ---- phase D: offsets / cursor / norm / sdeg ----
    {
        int base0 = blockIdx.x * CHUNK;
        int cnt = NN - base0; if (cnt > CHUNK) cnt = CHUNK;
        int v = (t < cnt && cnt > 0) ? g_deg[base0 + t] : 0;
        sm[t] = v;
        __syncthreads();
        for (int off = 1; off < NTHR; off <<= 1) {
            int x = (t >= off) ? sm[t - off] : 0;
            __syncthreads();
            sm[t] += x;
            __syncthreads();
        }
        int excl = sm[t] - v;
        int base = g_part[blockIdx.x];
        if (t < cnt && cnt > 0) {
            int i = base0 + t;
            int off = base + excl;
            g_off[i] = off;
            g_cursor[i] = off;
            int dc = (v > 0) ? v : 1;
            g_norm[i] = rsqrtf((float)dc);
            g_sdeg[i] = sqrtf((float)dc);
        }
        if (blockIdx.x == NCTA - 1 && t == 0) g_off[NN] = EE;
    }
    gbar();

    // ---- phase E: CSR fill + re-zero deg/stats ----
    for (int e = gtid; e < EE; e += T) {
        int p = atomicAdd(&g_cursor[dst[e]], 1);
        g_csr[p] = src[e];
    }
    if (gtid < NN) g_deg[gtid] = 0;       // T > NN, single stride covers
    if (gtid < 4 * HH) g_stats[gtid] = 0.0f;
    gbar();

    // ---- phases F-I: 4 propagation rounds ----
    gather_round(feat, g_z1, 1, gwarp, totalWarps, lane);
    gbar();
    gather_round(g_z1, g_z2, 0, gwarp, totalWarps, lane);
    gbar();
    gather_round(g_z2, g_z3, 0, gwarp, totalWarps, lane);
    gbar();
    gather_round(g_z3, g_z4, 0, gwarp, totalWarps, lane);
    (void)smx;
}

// B paired-fragment address
__device__ __forceinline__ uint32_t bpair_off(int warpN64, int p, int kc, int lane, int LDS) {
    int r = warpN64 + p * 16 + (lane & 7) + ((lane & 16) >> 1);
    int col = kc + (((lane & 15) >> 3) << 3);
    return (uint32_t)(r * LDS + col) * 2;
}

// ---------------- GEMM1: 128x256, K=64 (single-stage) -----------------------
__global__ __launch_bounds__(512, 1) void k_mma1(
    const float* __restrict__ Z1, const float* __restrict__ Z2,
    const float* __restrict__ Z3, const float* __restrict__ Z4,
    const float* __restrict__ feat,
    const __nv_bfloat16* __restrict__ Bhi, const __nv_bfloat16* __restrict__ Blo,
    float* __restrict__ out, float* __restrict__ stats)
{
    constexpr int KDIM = DD, LDS = 40;
    extern __shared__ __align__(16) char smem[];
    __nv_bfloat16* sAhi = (__nv_bfloat16*)(smem);
    __nv_bfloat16* sAlo = (__nv_bfloat16*)(smem + 10240);
    __nv_bfloat16* sBhi = (__nv_bfloat16*)(smem + 20480);
    __nv_bfloat16* sBlo = (__nv_bfloat16*)(smem + 40960);

    int tid = threadIdx.x, lane = tid & 31, wid = tid >> 5;
    int warp_m = wid & 3, warp_n = wid >> 2;
    int row0 = blockIdx.x * 128;

    float c[2][8][4];
#pragma unroll
    for (int mt = 0; mt < 2; mt++)
#pragma unroll
        for (int nt = 0; nt < 8; nt++)
#pragma unroll
            for (int q = 0; q < 4; q++) c[mt][nt][q] = 0.0f;

    uint32_t aAhi = smem_u32(sAhi), aAlo = smem_u32(sAlo);
    uint32_t aBhi = smem_u32(sBhi), aBlo = smem_u32(sBlo);

    int qa = tid & 7, ra0 = tid >> 3;
    int qb = tid & 3, nb0 = tid >> 2;
    bool val0 = (row0 + ra0) < NN;
    bool val1 = (row0 + ra0 + 64) < NN;
    float sd0 = val0 ? (0.2375f * g_sdeg[row0 + ra0]) : 0.f;
    float sd1 = val1 ? (0.2375f * g_sdeg[row0 + ra0 + 64]) : 0.f;

#pragma unroll 1
    for (int ch = 0; ch < KDIM / 32; ch++) {
        int k0 = ch * 32;
#pragma unroll
        for (int it = 0; it < 2; it++) {
            int r = ra0 + it * 64;
            bool valid = it ? val1 : val0;
            float sd = it ? sd1 : sd0;
            float4 v = make_float4(0, 0, 0, 0);
            if (valid) {
                size_t o = (size_t)(row0 + r) * KDIM + k0 + qa * 4;
                float4 z1 = *(const float4*)(Z1 + o);
                float4 z2 = *(const float4*)(Z2 + o);
                float4 z3 = *(const float4*)(Z3 + o);
                float4 z4 = *(const float4*)(Z4 + o);
                float4 f = *(const float4*)(feat + o);
                v.x = sd * (z1.x + z2.x + z3.x + z4.x) + 0.05f * f.x;
                v.y = sd * (z1.y + z2.y + z3.y + z4.y) + 0.05f * f.y;
                v.z = sd * (z1.z + z2.z + z3.z + z4.z) + 0.05f * f.z;
                v.w = sd * (z1.w + z2.w + z3.w + z4.w) + 0.05f * f.w;
            }
            uint32_t h01, l01, h23, l23;
            split_pack(v.x, v.y, h01, l01);
            split_pack(v.z, v.w, h23, l23);
            *(uint2*)&sAhi[r * LDS + qa * 4] = make_uint2(h01, h23);
            *(uint2*)&sAlo[r * LDS + qa * 4] = make_uint2(l01, l23);
        }
#pragma unroll
        for (int it = 0; it < 2; it++) {
            int n = nb0 + it * 128;
            size_t goff = (size_t)n * KDIM + k0 + qb * 8;
            *(uint4*)&sBhi[n * LDS + qb * 8] = *(const uint4*)(Bhi + goff);
            *(uint4*)&sBlo[n * LDS + qb * 8] = *(const uint4*)(Blo + goff);
        }
        __syncthreads();
#pragma unroll
        for (int ks = 0; ks < 2; ks++) {
            int kc = ks * 16;
            uint32_t ah[2][4], al[2][4];
#pragma unroll
            for (int mt = 0; mt < 2; mt++) {
                int r = warp_m * 32 + mt * 16 + (lane & 15);
                uint32_t off = (uint32_t)(r * LDS + kc + ((lane >> 4) << 3)) * 2;
                ldm_x4(ah[mt], aAhi + off);
                ldm_x4(al[mt], aAlo + off);
            }
#pragma unroll
            for (int p = 0; p < 4; p++) {
                uint32_t off = bpair_off(warp_n * 64, p, kc, lane, LDS);
                uint32_t bh[4], bl[4];
                ldm_x4(bh, aBhi + off);
                ldm_x4(bl, aBlo + off);
#pragma unroll
                for (int half = 0; half < 2; half++) {
                    int nt = p * 2 + half;
#pragma unroll
                    for (int mt = 0; mt < 2; mt++) {
                        mma_bf16(c[mt][nt], ah[mt], bh + half * 2);
                        mma_bf16(c[mt][nt], al[mt], bh + half * 2);
                        mma_bf16(c[mt][nt], ah[mt], bl + half * 2);
                    }
                }
            }
        }
        __syncthreads();
    }
    int colb = warp_n * 64 + ((lane & 3) << 1);
    int rb = row0 + warp_m * 32 + (lane >> 2);
#pragma unroll
    for (int mt = 0; mt < 2; mt++) {
        int gr = rb + mt * 16;
#pragma unroll
        for (int nt = 0; nt < 8; nt++) {
            int col = colb + nt * 8;
            if (gr < NN)
                *(float2*)(out + (size_t)gr * HH + col) = make_float2(c[mt][nt][0], c[mt][nt][1]);
            if (gr + 8 < NN)
                *(float2*)(out + (size_t)(gr + 8) * HH + col) = make_float2(c[mt][nt][2], c[mt][nt][3]);
        }
    }
#pragma unroll
    for (int nt = 0; nt < 8; nt++) {
        float s0 = c[0][nt][0] + c[0][nt][2] + c[1][nt][0] + c[1][nt][2];
        float s1 = c[0][nt][1] + c[0][nt][3] + c[1][nt][1] + c[1][nt][3];
        float q0 = c[0][nt][0] * c[0][nt][0] + c[0][nt][2] * c[0][nt][2] +
                   c[1][nt][0] * c[1][nt][0] + c[1][nt][2] * c[1][nt][2];
        float q1 = c[0][nt][1] * c[0][nt][1] + c[0][nt][3] * c[0][nt][3] +
                   c[1][nt][1] * c[1][nt][1] + c[1][nt][3] * c[1][nt][3];
#pragma unroll
        for (int m = 4; m < 32; m <<= 1) {
            s0 += __shfl_xor_sync(0xffffffffu, s0, m);
            s1 += __shfl_xor_sync(0xffffffffu, s1, m);
            q0 += __shfl_xor_sync(0xffffffffu, q0, m);
            q1 += __shfl_xor_sync(0xffffffffu, q1, m);
        }
        if (lane < 4) {
            int col = warp_n * 64 + nt * 8 + lane * 2;
            atomicAdd(&stats[col], s0);
            atomicAdd(&stats[col + 1], s1);
            atomicAdd(&stats[HH + col], q0);
            atomicAdd(&stats[HH + col + 1], q1);
        }
    }
}

// ---------------- GEMM2: 128x256, K=256; double-buffered, fused BN prologue --
__global__ __launch_bounds__(512, 1) void k_mma2(
    const float* __restrict__ A,
    const __nv_bfloat16* __restrict__ Bhi, const __nv_bfloat16* __restrict__ Blo,
    const float* __restrict__ stats, const float* __restrict__ gamma,
    const float* __restrict__ beta,
    float* __restrict__ out, float* __restrict__ statsOut)
{
    constexpr int KDIM = HH, LDS = 40;
    extern __shared__ __align__(16) char smem[];
    float* sBnA = (float*)(smem + 122880);
    float* sBnC = (float*)(smem + 123904);

    int tid = threadIdx.x, lane = tid & 31, wid = tid >> 5;
    int warp_m = wid & 3, warp_n = wid >> 2;
    int row0 = blockIdx.x * 128;

    if (tid < HH) {
        float inv = 1.0f / (float)NN;
        float mean = stats[tid] * inv;
        float var = stats[HH + tid] * inv - mean * mean;
        float rstd = rsqrtf(var + BNEPS);
        float a = gamma[tid] * rstd;
        sBnA[tid] = a;
        sBnC[tid] = beta[tid] - a * mean;
    }

    float c[2][8][4];
#pragma unroll
    for (int mt = 0; mt < 2; mt++)
#pragma unroll
        for (int nt = 0; nt < 8; nt++)
#pragma unroll
            for (int q = 0; q < 4; q++) c[mt][nt][q] = 0.0f;

    uint32_t sb = smem_u32(smem);
    int qa = tid & 7, ra0 = tid >> 3;
    int qb = tid & 3, nb0 = tid >> 2;
    bool val0 = (row0 + ra0) < NN;
    bool val1 = (row0 + ra0 + 64) < NN;
    const float* Arow0 = A + (size_t)(row0 + ra0) * KDIM + qa * 4;
    const float* Arow1 = Arow0 + (size_t)64 * KDIM;
    const __nv_bfloat16* B0h = Bhi + (size_t)nb0 * KDIM + qb * 8;
    const __nv_bfloat16* B1h = B0h + (size_t)128 * KDIM;
    const __nv_bfloat16* B0l = Blo + (size_t)nb0 * KDIM + qb * 8;
    const __nv_bfloat16* B1l = B0l + (size_t)128 * KDIM;

    const int NCH = KDIM / 32;
    float4 ra[2];
    uint4 rbh[2], rbl[2];
    ra[0] = val0 ? *(const float4*)(Arow0) : make_float4(0, 0, 0, 0);
    ra[1] = val1 ? *(const float4*)(Arow1) : make_float4(0, 0, 0, 0);
    rbh[0] = *(const uint4*)(B0h); rbh[1] = *(const uint4*)(B1h);
    rbl[0] = *(const uint4*)(B0l); rbl[1] = *(const uint4*)(B1l);

    __syncthreads();

    {
        float4 s = *(const float4*)&sBnA[qa * 4];
        float4 h = *(const float4*)&sBnC[qa * 4];
#pragma unroll
        for (int it = 0; it < 2; it++) {
            float4 v;
            v.x = fmaxf(fmaf(ra[it].x, s.x, h.x), 0.f);
            v.y = fmaxf(fmaf(ra[it].y, s.y, h.y), 0.f);
            v.z = fmaxf(fmaf(ra[it].z, s.z, h.z), 0.f);
            v.w = fmaxf(fmaf(ra[it].w, s.w, h.w), 0.f);
            if (!(it ? val1 : val0)) v = make_float4(0, 0, 0, 0);
            uint32_t h01, l01, h23, l23;
            split_pack(v.x, v.y, h01, l01);
            split_pack(v.z, v.w, h23, l23);
            int r = ra0 + it * 64;
            *(uint2*)(smem + (r * LDS + qa * 4) * 2) = make_uint2(h01, h23);
            *(uint2*)(smem + 10240 + (r * LDS + qa * 4) * 2) = make_uint2(l01, l23);
        }
#pragma unroll
        for (int it = 0; it < 2; it++) {
            int n = nb0 + it * 128;
            *(uint4*)(smem + 40960 + (n * LDS + qb * 8) * 2) = rbh[it];
            *(uint4*)(smem + 40960 + 20480 + (n * LDS + qb * 8) * 2) = rbl[it];
        }
    }

#pragma unroll 1
    for (int ch = 0; ch < NCH; ch++) {
        __syncthreads();
        if (ch + 1 < NCH) {
            int kn = (ch + 1) * 32;
            ra[0] = val0 ? *(const float4*)(Arow0 + kn) : make_float4(0, 0, 0, 0);
            ra[1] = val1 ? *(const float4*)(Arow1 + kn) : make_float4(0, 0, 0, 0);
            rbh[0] = *(const uint4*)(B0h + kn); rbh[1] = *(const uint4*)(B1h + kn);
            rbl[0] = *(const uint4*)(B0l + kn); rbl[1] = *(const uint4*)(B1l + kn);
        }
        uint32_t stA = (uint32_t)(ch & 1) * 20480;
        uint32_t stB = 40960 + (uint32_t)(ch & 1) * 40960;
#pragma unroll
        for (int ks = 0; ks < 2; ks++) {
            int kc = ks * 16;
            uint32_t ah[2][4], al[2][4];
#pragma unroll
            for (int mt = 0; mt < 2; mt++) {
                int r = warp_m * 32 + mt * 16 + (lane & 15);
                uint32_t off = (uint32_t)(r * LDS + kc + ((lane >> 4) << 3)) * 2;
                ldm_x4(ah[mt], sb + stA + off);
                ldm_x4(al[mt], sb + stA + 10240 + off);
            }
#pragma unroll
            for (int p = 0; p < 4; p++) {
                uint32_t off = bpair_off(warp_n * 64, p, kc, lane, LDS);
                uint32_t bh[4], bl[4];
                ldm_x4(bh, sb + stB + off);
                ldm_x4(bl, sb + stB + 20480 + off);
#pragma unroll
                for (int half = 0; half < 2; half++) {
                    int nt = p * 2 + half;
#pragma unroll
                    for (int mt = 0; mt < 2; mt++) {
                        mma_bf16(c[mt][nt], ah[mt], bh + half * 2);
                        mma_bf16(c[mt][nt], al[mt], bh + half * 2);
                        mma_bf16(c[mt][nt], ah[mt], bl + half * 2);
                    }
                }
            }
        }
        if (ch + 1 < NCH) {
            int kn = (ch + 1) * 32;
            uint32_t nsA = (uint32_t)((ch + 1) & 1) * 20480;
            uint32_t nsB = 40960 + (uint32_t)((ch + 1) & 1) * 40960;
            float4 s = *(const float4*)&sBnA[kn + qa * 4];
            float4 h = *(const float4*)&sBnC[kn + qa * 4];
#pragma unroll
            for (int it = 0; it < 2; it++) {
                float4 v;
                v.x = fmaxf(fmaf(ra[it].x, s.x, h.x), 0.f);
                v.y = fmaxf(fmaf(ra[it].y, s.y, h.y), 0.f);
                v.z = fmaxf(fmaf(ra[it].z, s.z, h.z), 0.f);
                v.w = fmaxf(fmaf(ra[it].w, s.w, h.w), 0.f);
                if (!(it ? val1 : val0)) v = make_float4(0, 0, 0, 0);
                uint32_t h01, l01, h23, l23;
                split_pack(v.x, v.y, h01, l01);
                split_pack(v.z, v.w, h23, l23);
                int r = ra0 + it * 64;
                *(uint2*)(smem + nsA + (r * LDS + qa * 4) * 2) = make_uint2(h01, h23);
                *(uint2*)(smem + nsA + 10240 + (r * LDS + qa * 4) * 2) = make_uint2(l01, l23);
            }
#pragma unroll
            for (int it = 0; it < 2; it++) {
                int n = nb0 + it * 128;
                *(uint4*)(smem + nsB + (n * LDS + qb * 8) * 2) = rbh[it];
                *(uint4*)(smem + nsB + 20480 + (n * LDS + qb * 8) * 2) = rbl[it];
            }
        }
    }

    int colb = warp_n * 64 + ((lane & 3) << 1);
    int rb = row0 + warp_m * 32 + (lane >> 2);
#pragma unroll
    for (int mt = 0; mt < 2; mt++) {
        int gr = rb + mt * 16;
#pragma unroll
        for (int nt = 0; nt < 8; nt++) {
            int col = colb + nt * 8;
            if (gr < NN)
                *(float2*)(out + (size_t)gr * HH + col) = make_float2(c[mt][nt][0], c[mt][nt][1]);
            if (gr + 8 < NN)
                *(float2*)(out + (size_t)(gr + 8) * HH + col) = make_float2(c[mt][nt][2], c[mt][nt][3]);
        }
    }
#pragma unroll
    for (int nt = 0; nt < 8; nt++) {
        float s0 = c[0][nt][0] + c[0][nt][2] + c[1][nt][0] + c[1][nt][2];
        float s1 = c[0][nt][1] + c[0][nt][3] + c[1][nt][1] + c[1][nt][3];
        float q0 = c[0][nt][0] * c[0][nt][0] + c[0][nt][2] * c[0][nt][2] +
                   c[1][nt][0] * c[1][nt][0] + c[1][nt][2] * c[1][nt][2];
        float q1 = c[0][nt][1] * c[0][nt][1] + c[0][nt][3] * c[0][nt][3] +
                   c[1][nt][1] * c[1][nt][1] + c[1][nt][3] * c[1][nt][3];
#pragma unroll
        for (int m = 4; m < 32; m <<= 1) {
            s0 += __shfl_xor_sync(0xffffffffu, s0, m);
            s1 += __shfl_xor_sync(0xffffffffu, s1, m);
            q0 += __shfl_xor_sync(0xffffffffu, q0, m);
            q1 += __shfl_xor_sync(0xffffffffu, q1, m);
        }
        if (lane < 4) {
            int col = warp_n * 64 + nt * 8 + lane * 2;
            atomicAdd(&statsOut[col], s0);
            atomicAdd(&statsOut[col + 1], s1);
            atomicAdd(&statsOut[HH + col], q0);
            atomicAdd(&statsOut[HH + col + 1], q1);
        }
    }
}

// ---------------- GEMM3 (K=256, N=40): double-buffered, fused BN prologue ----
__global__ __launch_bounds__(256) void k_mma3(
    const float* __restrict__ A,
    const __nv_bfloat16* __restrict__ Bhi, const __nv_bfloat16* __restrict__ Blo,
    const float* __restrict__ stats, const float* __restrict__ gamma,
    const float* __restrict__ beta,
    const float* __restrict__ bias, float* __restrict__ out)
{
    constexpr int KDIM = 256, NTILE = 64, LDS = 40;
    constexpr int WN = NTILE / 4, NT8 = WN / 8;
    extern __shared__ __align__(16) char smem[];
    float* sBnA = (float*)(smem + 61440);
    float* sBnC = (float*)(smem + 62464);

    int tid = threadIdx.x, lane = tid & 31, wid = tid >> 5;
    int warp_m = wid & 1, warp_n = wid >> 1;
    int row0 = blockIdx.x * 128;

    if (tid < HH) {
        float inv = 1.0f / (float)NN;
        float mean = stats[tid] * inv;
        float var = stats[HH + tid] * inv - mean * mean;
        float rstd = rsqrtf(var + BNEPS);
        float a = gamma[tid] * rstd;
        sBnA[tid] = a;
        sBnC[tid] = beta[tid] - a * mean;
    }

    float c[4][NT8][4];
#pragma unroll
    for (int mt = 0; mt < 4; mt++)
#pragma unroll
        for (int nt = 0; nt < NT8; nt++)
#pragma unroll
            for (int q = 0; q < 4; q++) c[mt][nt][q] = 0.0f;

    uint32_t sb = smem_u32(smem);
    const int NCH = KDIM / 32;
    int qa = tid & 7;
    int rA[4]; bool vA[4];
#pragma unroll
    for (int it = 0; it < 4; it++) {
        rA[it] = (tid + it * 256) >> 3;
        vA[it] = (row0 + rA[it]) < NN;
    }
    int nb = tid >> 2, qb = tid & 3;

    float4 ra[4];
    uint4 rbh, rbl;
#pragma unroll
    for (int it = 0; it < 4; it++)
        ra[it] = vA[it] ? *(const float4*)(A + (size_t)(row0 + rA[it]) * KDIM + qa * 4)
                        : make_float4(0, 0, 0, 0);
    rbh = *(const uint4*)(Bhi + (size_t)nb * KDIM + qb * 8);
    rbl = *(const uint4*)(Blo + (size_t)nb * KDIM + qb * 8);

    __syncthreads();

    {
        float4 s = *(const float4*)&sBnA[qa * 4];
        float4 h = *(const float4*)&sBnC[qa * 4];
#pragma unroll
        for (int it = 0; it < 4; it++) {
            float4 v;
            v.x = fmaxf(fmaf(ra[it].x, s.x, h.x), 0.f);
            v.y = fmaxf(fmaf(ra[it].y, s.y, h.y), 0.f);
            v.z = fmaxf(fmaf(ra[it].z, s.z, h.z), 0.f);
            v.w = fmaxf(fmaf(ra[it].w, s.w, h.w), 0.f);
            if (!vA[it]) v = make_float4(0, 0, 0, 0);
            uint32_t h01, l01, h23, l23;
            split_pack(v.x, v.y, h01, l01);
            split_pack(v.z, v.w, h23, l23);
            *(uint2*)(smem + (rA[it] * LDS + qa * 4) * 2) = make_uint2(h01, h23);
            *(uint2*)(smem + 10240 + (rA[it] * LDS + qa * 4) * 2) = make_uint2(l01, l23);
        }
        *(uint4*)(smem + 40960 + (nb * LDS + qb * 8) * 2) = rbh;
        *(uint4*)(smem + 40960 + 5120 + (nb * LDS + qb * 8) * 2) = rbl;
    }

#pragma unroll 1
    for (int ch = 0; ch < NCH; ch++) {
        __syncthreads();
        if (ch + 1 < NCH) {
            int kn = (ch + 1) * 32;
#pragma unroll
            for (int it = 0; it < 4; it++)
                ra[it] = vA[it] ? *(const float4*)(A + (size_t)(row0 + rA[it]) * KDIM + kn + qa * 4)
                                : make_float4(0, 0, 0, 0);
            rbh = *(const uint4*)(Bhi + (size_t)nb * KDIM + kn + qb * 8);
            rbl = *(const uint4*)(Blo + (size_t)nb * KDIM + kn + qb * 8);
        }
        uint32_t stA = (uint32_t)(ch & 1) * 20480;
        uint32_t stB = 40960 + (uint32_t)(ch & 1) * 10240;
#pragma unroll
        for (int ks = 0; ks < 2; ks++) {
            int kc = ks * 16;
            uint32_t bh[4], bl[4];
            uint32_t off = bpair_off(warp_n * WN, 0, kc, lane, LDS);
            ldm_x4(bh, sb + stB + off);
            ldm_x4(bl, sb + stB + 5120 + off);
#pragma unroll
            for (int mt = 0; mt < 4; mt++) {
                int r = warp_m * 64 + mt * 16 + (lane & 15);
                uint32_t aoff = (uint32_t)(r * LDS + kc + ((lane >> 4) << 3)) * 2;
                uint32_t ah[4], al[4];
                ldm_x4(ah, sb + stA + aoff);
                ldm_x4(al, sb + stA + 10240 + aoff);
#pragma unroll
                for (int half = 0; half < 2; half++) {
                    mma_bf16(c[mt][half], ah, bh + half * 2);
                    mma_bf16(c[mt][half], al, bh + half * 2);
                    mma_bf16(c[mt][half], ah, bl + half * 2);
                }
            }
        }
        if (ch + 1 < NCH) {
            int kn = (ch + 1) * 32;
            uint32_t nsA = (uint32_t)((ch + 1) & 1) * 20480;
            uint32_t nsB = 40960 + (uint32_t)((ch + 1) & 1) * 10240;
            float4 s = *(const float4*)&sBnA[kn + qa * 4];
            float4 h = *(const float4*)&sBnC[kn + qa * 4];
#pragma unroll
            for (int it = 0; it < 4; it++) {
                float4 v;
                v.x = fmaxf(fmaf(ra[it].x, s.x, h.x), 0.f);
                v.y = fmaxf(fmaf(ra[it].y, s.y, h.y), 0.f);
                v.z = fmaxf(fmaf(ra[it].z, s.z, h.z), 0.f);
                v.w = fmaxf(fmaf(ra[it].w, s.w, h.w), 0.f);
                if (!vA[it]) v = make_float4(0, 0, 0, 0);
                uint32_t h01, l01, h23, l23;
                split_pack(v.x, v.y, h01, l01);
                split_pack(v.z, v.w, h23, l23);
                *(uint2*)(smem + nsA + (rA[it] * LDS + qa * 4) * 2) = make_uint2(h01, h23);
                *(uint2*)(smem + nsA + 10240 + (rA[it] * LDS + qa * 4) * 2) = make_uint2(l01, l23);
            }
            *(uint4*)(smem + nsB + (nb * LDS + qb * 8) * 2) = rbh;
            *(uint4*)(smem + nsB + 5120 + (nb * LDS + qb * 8) * 2) = rbl;
        }
    }

    int colbase = warp_n * WN + ((lane & 3) << 1);
    int rbase = row0 + warp_m * 64 + (lane >> 2);
#pragma unroll
    for (int mt = 0; mt < 4; mt++) {
        int r0g = rbase + mt * 16;
#pragma unroll
        for (int nt = 0; nt < NT8; nt++) {
            int col = colbase + nt * 8;
            if (col >= CC) continue;
            float bx = bias[col], by = bias[col + 1];
            if (r0g < NN)
                *(float2*)(out + (size_t)r0g * CC + col) =
                    make_float2(c[mt][nt][0] + bx, c[mt][nt][1] + by);
            if (r0g + 8 < NN)
                *(float2*)(out + (size_t)(r0g + 8) * CC + col) =
                    make_float2(c[mt][nt][2] + bx, c[mt][nt][3] + by);
        }
    }
}

// ---------------- launch ----------------
extern "C" void kernel_launch(void* const* d_in, const int* in_sizes, int n_in,
                              void* d_out, int out_size) {
    const float* feat = (const float*)d_in[0];
    const int*   src  = (const int*)d_in[1];
    const int*   dst  = (const int*)d_in[2];
    const float* W1   = (const float*)d_in[3];
    const float* g1   = (const float*)d_in[5];
    const float* be1  = (const float*)d_in[6];
    const float* W2   = (const float*)d_in[7];
    const float* g2   = (const float*)d_in[9];
    const float* be2  = (const float*)d_in[10];
    const float* W3   = (const float*)d_in[11];
    const float* b3   = (const float*)d_in[12];
    float* out = (float*)d_out;

    float *p_z1, *p_z2, *p_z3, *p_z4, *p_y1, *p_y2, *p_stats;
    __nv_bfloat16 *p_w1h, *p_w1l, *p_w2h, *p_w2l, *p_w3h, *p_w3l;
    cudaGetSymbolAddress((void**)&p_z1, g_z1);
    cudaGetSymbolAddress((void**)&p_z2, g_z2);
    cudaGetSymbolAddress((void**)&p_z3, g_z3);
    cudaGetSymbolAddress((void**)&p_z4, g_z4);
    cudaGetSymbolAddress((void**)&p_y1, g_y1);
    cudaGetSymbolAddress((void**)&p_y2, g_y2);
    cudaGetSymbolAddress((void**)&p_stats, g_stats);
    cudaGetSymbolAddress((void**)&p_w1h, g_w1h);
    cudaGetSymbolAddress((void**)&p_w1l, g_w1l);
    cudaGetSymbolAddress((void**)&p_w2h, g_w2h);
    cudaGetSymbolAddress((void**)&p_w2l, g_w2l);
    cudaGetSymbolAddress((void**)&p_w3h, g_w3h);
    cudaGetSymbolAddress((void**)&p_w3l, g_w3l);

    const int SM1 = 61440;
    const int SM2 = 124928;
    const int SM3 = 63488;
    cudaFuncSetAttribute((const void*)k_mma1,
                         cudaFuncAttributeMaxDynamicSharedMemorySize, SM1);
    cudaFuncSetAttribute((const void*)k_mma2,
                         cudaFuncAttributeMaxDynamicSharedMemorySize, SM2);
    cudaFuncSetAttribute((const void*)k_mma3,
                         cudaFuncAttributeMaxDynamicSharedMemorySize, SM3);

    // one persistent kernel: CSR build + 4 propagation rounds
    k_mega<<<NCTA, NTHR>>>(src, dst, feat, W1, W2, W3);

    int mgrid = (NN + 127) / 128;
    k_mma1<<<mgrid, 512, SM1>>>(p_z1, p_z2, p_z3, p_z4, feat,
                                p_w1h, p_w1l, p_y1, p_stats);
    k_mma2<<<mgrid, 512, SM2>>>(p_y1, p_w2h, p_w2l,
                                p_stats, g1, be1, p_y2, p_stats + 2 * HH);
    k_mma3<<<mgrid, 256, SM3>>>(p_y2, p_w3h, p_w3l,
                                p_stats + 2 * HH, g2, be2, b3, out);
}

// round 12
// speedup vs baseline: 1.0277x; 1.0277x over previous
#include <cuda_runtime.h>
#include <cuda_bf16.h>
#include <math.h>
#include <stdint.h>

#define NN 100000
#define EE 1250000
#define DD 64
#define HH 256
#define CC 40
#define BNEPS 1e-5f
#define NB_SCAN 98

// ---------------- device scratch ----------------
__device__ float g_z1[NN * DD];
__device__ float g_z2[NN * DD];
__device__ float g_z3[NN * DD];
__device__ float g_z4[NN * DD];
__device__ float g_norm[NN];
__device__ float g_sdeg[NN];
__device__ int   g_deg[NN];       // zero at load; re-zeroed by k_gather<1> each call
__device__ int   g_off[NN + 1];
__device__ int   g_cursor[NN];
__device__ int   g_csr[EE];
__device__ int   g_bsum[NB_SCAN];
__device__ float g_y1[NN * HH];
__device__ float g_y2[NN * HH];
__device__ float g_stats[4 * HH]; // zero at load; re-zeroed by k_gather<1> each call
__device__ __nv_bfloat16 g_w1h[HH * DD], g_w1l[HH * DD];
__device__ __nv_bfloat16 g_w2h[HH * HH], g_w2l[HH * HH];
__device__ __nv_bfloat16 g_w3h[64 * HH], g_w3l[64 * HH];

// ---------------- helpers ----------------
__device__ __forceinline__ uint32_t smem_u32(const void* p) {
    uint32_t a;
    asm("{ .reg .u64 t; cvta.to.shared.u64 t, %1; cvt.u32.u64 %0, t; }" : "=r"(a) : "l"(p));
    return a;
}
__device__ __forceinline__ void ldm_x4(uint32_t* r, uint32_t addr) {
    asm volatile("ldmatrix.sync.aligned.m8n8.x4.shared.b16 {%0,%1,%2,%3}, [%4];"
                 : "=r"(r[0]), "=r"(r[1]), "=r"(r[2]), "=r"(r[3]) : "r"(addr));
}
__device__ __forceinline__ void mma_bf16(float* c, const uint32_t* a, const uint32_t* b) {
    asm volatile(
        "mma.sync.aligned.m16n8k16.row.col.f32.bf16.bf16.f32 "
        "{%0,%1,%2,%3}, {%4,%5,%6,%7}, {%8,%9}, {%0,%1,%2,%3};"
        : "+f"(c[0]), "+f"(c[1]), "+f"(c[2]), "+f"(c[3])
        : "r"(a[0]), "r"(a[1]), "r"(a[2]), "r"(a[3]), "r"(b[0]), "r"(b[1]));
}
__device__ __forceinline__ void split_pack(float x, float y, uint32_t& hi, uint32_t& lo) {
    uint32_t h;
    asm("cvt.rn.bf16x2.f32 %0, %1, %2;" : "=r"(h) : "f"(y), "f"(x));
    float xb = __uint_as_float(h << 16);
    float yb = __uint_as_float(h & 0xffff0000u);
    float rx = x - xb, ry = y - yb;
    uint32_t l;
    asm("cvt.rn.bf16x2.f32 %0, %1, %2;" : "=r"(l) : "f"(ry), "f"(rx));
    hi = h;
    lo = l;
}
__device__ __forceinline__ void wsplit(const float* W, __nv_bfloat16* hi, __nv_bfloat16* lo,
                                       int idx, int K, int Nsrc) {
    int n = idx / K, k = idx - n * K;
    float v = (n < Nsrc) ? W[(size_t)k * Nsrc + n] : 0.0f;
    __nv_bfloat16 h = __float2bfloat16(v);
    hi[idx] = h;
    lo[idx] = __float2bfloat16(v - __bfloat162float(h));
}

// ---------------- count (+ fused weight split) ----------------
__global__ void k_count(const int* __restrict__ dst, const float* __restrict__ W1,
                        const float* __restrict__ W2, const float* __restrict__ W3) {
    int e = blockIdx.x * blockDim.x + threadIdx.x;
    if (e < EE) atomicAdd(&g_deg[dst[e]], 1);
    if (e < HH * DD) wsplit(W1, g_w1h, g_w1l, e, DD, HH);
    else if (e < HH * DD + HH * HH) wsplit(W2, g_w2h, g_w2l, e - HH * DD, HH, HH);
    else if (e < HH * DD + HH * HH + 64 * HH)
        wsplit(W3, g_w3h, g_w3l, e - HH * DD - HH * HH, HH, CC);
}
__global__ void k_scan1() {
    __shared__ int s[1024];
    int t = threadIdx.x;
    int i = blockIdx.x * 1024 + t;
    int v = (i < NN) ? g_deg[i] : 0;
    s[t] = v;
    __syncthreads();
    for (int off = 1; off < 1024; off <<= 1) {
        int x = (t >= off) ? s[t - off] : 0;
        __syncthreads();
        s[t] += x;
        __syncthreads();
    }
    if (i < NN) g_off[i] = s[t] - v;
    if (t == 1023) g_bsum[blockIdx.x] = s[1023];
}
__global__ void k_scan3() {
    __shared__ int sb[128];
    int t = threadIdx.x;
    if (t < 128) sb[t] = (t < NB_SCAN) ? g_bsum[t] : 0;
    __syncthreads();
    for (int off = 1; off < 128; off <<= 1) {
        int x = 0;
        if (t < 128 && t >= off) x = sb[t - off];
        __syncthreads();
        if (t < 128) sb[t] += x;
        __syncthreads();
    }
    int base = (blockIdx.x > 0) ? sb[blockIdx.x - 1] : 0;
    int i = blockIdx.x * 1024 + t;
    if (i < NN) {
        int off = g_off[i] + base;
        g_off[i] = off;
        g_cursor[i] = off;
        int d = g_deg[i];
        int dc = (d > 0) ? d : 1;
        g_norm[i] = rsqrtf((float)dc);
        g_sdeg[i] = sqrtf((float)dc);
    }
    if (i == NN) g_off[NN] = EE;
}
__global__ void k_fill(const int* __restrict__ src, const int* __restrict__ dst) {
    int e = blockIdx.x * blockDim.x + threadIdx.x;
    if (e < EE) {
        int p = atomicAdd(&g_cursor[dst[e]], 1);
        g_csr[p] = src[e];
    }
}

// ---------------- propagation ----------------
template <int FIRST>
__global__ __launch_bounds__(256) void k_gather(const float* __restrict__ zin,
                                                float* __restrict__ zout) {
    if (FIRST) {
        int gid = blockIdx.x * blockDim.x + threadIdx.x;
        if (gid < NN) g_deg[gid] = 0;
        if (gid < 4 * HH) g_stats[gid] = 0.0f;
    }
    int warp = (blockIdx.x * blockDim.x + threadIdx.x) >> 5;
    int lane = threadIdx.x & 31;
    if (warp >= NN) return;
    int beg = g_off[warp], end = g_off[warp + 1];
    int grp = lane >> 4, sub = lane & 15;
    const float4* z4 = (const float4*)zin;
    float4 a = make_float4(0.f, 0.f, 0.f, 0.f);
    float4 b = make_float4(0.f, 0.f, 0.f, 0.f);
    int e = beg + grp;
    for (; e + 2 < end; e += 4) {
        int j0 = g_csr[e], j1 = g_csr[e + 2];
        float4 v0 = z4[j0 * 16 + sub];
        float4 v1 = z4[j1 * 16 + sub];
        if (FIRST) {
            float n0 = g_norm[j0], n1 = g_norm[j1];
            a.x = fmaf(n0, v0.x, a.x); a.y = fmaf(n0, v0.y, a.y);
            a.z = fmaf(n0, v0.z, a.z); a.w = fmaf(n0, v0.w, a.w);
            b.x = fmaf(n1, v1.x, b.x); b.y = fmaf(n1, v1.y, b.y);
            b.z = fmaf(n1, v1.z, b.z); b.w = fmaf(n1, v1.w, b.w);
        } else {
            a.x += v0.x; a.y += v0.y; a.z += v0.z; a.w += v0.w;
            b.x += v1.x; b.y += v1.y; b.z += v1.z; b.w += v1.w;
        }
    }
    if (e < end) {
        int j = g_csr[e];
        float4 v = z4[j * 16 + sub];
        if (FIRST) {
            float nj = g_norm[j];
            a.x = fmaf(nj, v.x, a.x); a.y = fmaf(nj, v.y, a.y);
            a.z = fmaf(nj, v.z, a.z); a.w = fmaf(nj, v.w, a.w);
        } else {
            a.x += v.x; a.y += v.y; a.z += v.z; a.w += v.w;
        }
    }
    a.x += b.x; a.y += b.y; a.z += b.z; a.w += b.w;
    a.x += __shfl_xor_sync(0xffffffffu, a.x, 16);
    a.y += __shfl_xor_sync(0xffffffffu, a.y, 16);
    a.z += __shfl_xor_sync(0xffffffffu, a.z, 16);
    a.w += __shfl_xor_sync(0xffffffffu, a.w, 16);
    if (grp == 0) {
        float ni = g_norm[warp];
        float n2 = ni * ni;
        ((float4*)zout)[warp * 16 + sub] =
            make_float4(n2 * a.x, n2 * a.y, n2 * a.z, n2 * a.w);
    }
}

// B paired-fragment address
__device__ __forceinline__ uint32_t bpair_off(int warpN, int p, int kc, int lane, int LDS) {
    int r = warpN + p * 16 + (lane & 7) + ((lane & 16) >> 1);
    int col = kc + (((lane & 15) >> 3) << 3);
    return (uint32_t)(r * LDS + col) * 2;
}

// ---------------- GEMM1: 128x256, K=64 (single-stage) -----------------------
__global__ __launch_bounds__(512, 1) void k_mma1(
    const float* __restrict__ Z1, const float* __restrict__ Z2,
    const float* __restrict__ Z3, const float* __restrict__ Z4,
    const float* __restrict__ feat,
    const __nv_bfloat16* __restrict__ Bhi, const __nv_bfloat16* __restrict__ Blo,
    float* __restrict__ out, float* __restrict__ stats)
{
    constexpr int KDIM = DD, LDS = 40;
    extern __shared__ __align__(16) char smem[];
    __nv_bfloat16* sAhi = (__nv_bfloat16*)(smem);
    __nv_bfloat16* sAlo = (__nv_bfloat16*)(smem + 10240);
    __nv_bfloat16* sBhi = (__nv_bfloat16*)(smem + 20480);
    __nv_bfloat16* sBlo = (__nv_bfloat16*)(smem + 40960);

    int tid = threadIdx.x, lane = tid & 31, wid = tid >> 5;
    int warp_m = wid & 3, warp_n = wid >> 2;
    int row0 = blockIdx.x * 128;

    float c[2][8][4];
#pragma unroll
    for (int mt = 0; mt < 2; mt++)
#pragma unroll
        for (int nt = 0; nt < 8; nt++)
#pragma unroll
            for (int q = 0; q < 4; q++) c[mt][nt][q] = 0.0f;

    uint32_t aAhi = smem_u32(sAhi), aAlo = smem_u32(sAlo);
    uint32_t aBhi = smem_u32(sBhi), aBlo = smem_u32(sBlo);

    int qa = tid & 7, ra0 = tid >> 3;
    int qb = tid & 3, nb0 = tid >> 2;
    bool val0 = (row0 + ra0) < NN;
    bool val1 = (row0 + ra0 + 64) < NN;
    float sd0 = val0 ? (0.2375f * g_sdeg[row0 + ra0]) : 0.f;
    float sd1 = val1 ? (0.2375f * g_sdeg[row0 + ra0 + 64]) : 0.f;

#pragma unroll 1
    for (int ch = 0; ch < KDIM / 32; ch++) {
        int k0 = ch * 32;
#pragma unroll
        for (int it = 0; it < 2; it++) {
            int r = ra0 + it * 64;
            bool valid = it ? val1 : val0;
            float sd = it ? sd1 : sd0;
            float4 v = make_float4(0, 0, 0, 0);
            if (valid) {
                size_t o = (size_t)(row0 + r) * KDIM + k0 + qa * 4;
                float4 z1 = *(const float4*)(Z1 + o);
                float4 z2 = *(const float4*)(Z2 + o);
                float4 z3 = *(const float4*)(Z3 + o);
                float4 z4 = *(const float4*)(Z4 + o);
                float4 f = *(const float4*)(feat + o);
                v.x = sd * (z1.x + z2.x + z3.x + z4.x) + 0.05f * f.x;
                v.y = sd * (z1.y + z2.y + z3.y + z4.y) + 0.05f * f.y;
                v.z = sd * (z1.z + z2.z + z3.z + z4.z) + 0.05f * f.z;
                v.w = sd * (z1.w + z2.w + z3.w + z4.w) + 0.05f * f.w;
            }
            uint32_t h01, l01, h23, l23;
            split_pack(v.x, v.y, h01, l01);
            split_pack(v.z, v.w, h23, l23);
            *(uint2*)&sAhi[r * LDS + qa * 4] = make_uint2(h01, h23);
            *(uint2*)&sAlo[r * LDS + qa * 4] = make_uint2(l01, l23);
        }
#pragma unroll
        for (int it = 0; it < 2; it++) {
            int n = nb0 + it * 128;
            size_t goff = (size_t)n * KDIM + k0 + qb * 8;
            *(uint4*)&sBhi[n * LDS + qb * 8] = *(const uint4*)(Bhi + goff);
            *(uint4*)&sBlo[n * LDS + qb * 8] = *(const uint4*)(Blo + goff);
        }
        __syncthreads();
#pragma unroll
        for (int ks = 0; ks < 2; ks++) {
            int kc = ks * 16;
            uint32_t ah[2][4], al[2][4];
#pragma unroll
            for (int mt = 0; mt < 2; mt++) {
                int r = warp_m * 32 + mt * 16 + (lane & 15);
                uint32_t off = (uint32_t)(r * LDS + kc + ((lane >> 4) << 3)) * 2;
                ldm_x4(ah[mt], aAhi + off);
                ldm_x4(al[mt], aAlo + off);
            }
#pragma unroll
            for (int p = 0; p < 4; p++) {
                uint32_t off = bpair_off(warp_n * 64, p, kc, lane, LDS);
                uint32_t bh[4], bl[4];
                ldm_x4(bh, aBhi + off);
                ldm_x4(bl, aBlo + off);
#pragma unroll
                for (int half = 0; half < 2; half++) {
                    int nt = p * 2 + half;
#pragma unroll
                    for (int mt = 0; mt < 2; mt++) {
                        mma_bf16(c[mt][nt], ah[mt], bh + half * 2);
                        mma_bf16(c[mt][nt], al[mt], bh + half * 2);
                        mma_bf16(c[mt][nt], ah[mt], bl + half * 2);
                    }
                }
            }
        }
        __syncthreads();
    }
    int colb = warp_n * 64 + ((lane & 3) << 1);
    int rb = row0 + warp_m * 32 + (lane >> 2);
#pragma unroll
    for (int mt = 0; mt < 2; mt++) {
        int gr = rb + mt * 16;
#pragma unroll
        for (int nt = 0; nt < 8; nt++) {
            int col = colb + nt * 8;
            if (gr < NN)
                *(float2*)(out + (size_t)gr * HH + col) = make_float2(c[mt][nt][0], c[mt][nt][1]);
            if (gr + 8 < NN)
                *(float2*)(out + (size_t)(gr + 8) * HH + col) = make_float2(c[mt][nt][2], c[mt][nt][3]);
        }
    }
#pragma unroll
    for (int nt = 0; nt < 8; nt++) {
        float s0 = c[0][nt][0] + c[0][nt][2] + c[1][nt][0] + c[1][nt][2];
        float s1 = c[0][nt][1] + c[0][nt][3] + c[1][nt][1] + c[1][nt][3];
        float q0 = c[0][nt][0] * c[0][nt][0] + c[0][nt][2] * c[0][nt][2] +
                   c[1][nt][0] * c[1][nt][0] + c[1][nt][2] * c[1][nt][2];
        float q1 = c[0][nt][1] * c[0][nt][1] + c[0][nt][3] * c[0][nt][3] +
                   c[1][nt][1] * c[1][nt][1] + c[1][nt][3] * c[1][nt][3];
#pragma unroll
        for (int m = 4; m < 32; m <<= 1) {
            s0 += __shfl_xor_sync(0xffffffffu, s0, m);
            s1 += __shfl_xor_sync(0xffffffffu, s1, m);
            q0 += __shfl_xor_sync(0xffffffffu, q0, m);
            q1 += __shfl_xor_sync(0xffffffffu, q1, m);
        }
        if (lane < 4) {
            int col = warp_n * 64 + nt * 8 + lane * 2;
            atomicAdd(&stats[col], s0);
            atomicAdd(&stats[col + 1], s1);
            atomicAdd(&stats[HH + col], q0);
            atomicAdd(&stats[HH + col + 1], q1);
        }
    }
}

// ---------------- GEMM2: 128x256, K=256; double-buffered, fused BN prologue --
__global__ __launch_bounds__(512, 1) void k_mma2(
    const float* __restrict__ A,
    const __nv_bfloat16* __restrict__ Bhi, const __nv_bfloat16* __restrict__ Blo,
    const float* __restrict__ stats, const float* __restrict__ gamma,
    const float* __restrict__ beta,
    float* __restrict__ out, float* __restrict__ statsOut)
{
    constexpr int KDIM = HH, LDS = 40;
    extern __shared__ __align__(16) char smem[];
    float* sBnA = (float*)(smem + 122880);
    float* sBnC = (float*)(smem + 123904);

    int tid = threadIdx.x, lane = tid & 31, wid = tid >> 5;
    int warp_m = wid & 3, warp_n = wid >> 2;
    int row0 = blockIdx.x * 128;

    if (tid < HH) {
        float inv = 1.0f / (float)NN;
        float mean = stats[tid] * inv;
        float var = stats[HH + tid] * inv - mean * mean;
        float rstd = rsqrtf(var + BNEPS);
        float a = gamma[tid] * rstd;
        sBnA[tid] = a;
        sBnC[tid] = beta[tid] - a * mean;
    }

    float c[2][8][4];
#pragma unroll
    for (int mt = 0; mt < 2; mt++)
#pragma unroll
        for (int nt = 0; nt < 8; nt++)
#pragma unroll
            for (int q = 0; q < 4; q++) c[mt][nt][q] = 0.0f;

    uint32_t sb = smem_u32(smem);
    int qa = tid & 7, ra0 = tid >> 3;
    int qb = tid & 3, nb0 = tid >> 2;
    bool val0 = (row0 + ra0) < NN;
    bool val1 = (row0 + ra0 + 64) < NN;
    const float* Arow0 = A + (size_t)(row0 + ra0) * KDIM + qa * 4;
    const float* Arow1 = Arow0 + (size_t)64 * KDIM;
    const __nv_bfloat16* B0h = Bhi + (size_t)nb0 * KDIM + qb * 8;
    const __nv_bfloat16* B1h = B0h + (size_t)128 * KDIM;
    const __nv_bfloat16* B0l = Blo + (size_t)nb0 * KDIM + qb * 8;
    const __nv_bfloat16* B1l = B0l + (size_t)128 * KDIM;

    const int NCH = KDIM / 32;
    float4 ra[2];
    uint4 rbh[2], rbl[2];
    ra[0] = val0 ? *(const float4*)(Arow0) : make_float4(0, 0, 0, 0);
    ra[1] = val1 ? *(const float4*)(Arow1) : make_float4(0, 0, 0, 0);
    rbh[0] = *(const uint4*)(B0h); rbh[1] = *(const uint4*)(B1h);
    rbl[0] = *(const uint4*)(B0l); rbl[1] = *(const uint4*)(B1l);

    __syncthreads();

    {
        float4 s = *(const float4*)&sBnA[qa * 4];
        float4 h = *(const float4*)&sBnC[qa * 4];
#pragma unroll
        for (int it = 0; it < 2; it++) {
            float4 v;
            v.x = fmaxf(fmaf(ra[it].x, s.x, h.x), 0.f);
            v.y = fmaxf(fmaf(ra[it].y, s.y, h.y), 0.f);
            v.z = fmaxf(fmaf(ra[it].z, s.z, h.z), 0.f);
            v.w = fmaxf(fmaf(ra[it].w, s.w, h.w), 0.f);
            if (!(it ? val1 : val0)) v = make_float4(0, 0, 0, 0);
            uint32_t h01, l01, h23, l23;
            split_pack(v.x, v.y, h01, l01);
            split_pack(v.z, v.w, h23, l23);
            int r = ra0 + it * 64;
            *(uint2*)(smem + (r * LDS + qa * 4) * 2) = make_uint2(h01, h23);
            *(uint2*)(smem + 10240 + (r * LDS + qa * 4) * 2) = make_uint2(l01, l23);
        }
#pragma unroll
        for (int it = 0; it < 2; it++) {
            int n = nb0 + it * 128;
            *(uint4*)(smem + 40960 + (n * LDS + qb * 8) * 2) = rbh[it];
            *(uint4*)(smem + 40960 + 20480 + (n * LDS + qb * 8) * 2) = rbl[it];
        }
    }

#pragma unroll 1
    for (int ch = 0; ch < NCH; ch++) {
        __syncthreads();
        if (ch + 1 < NCH) {
            int kn = (ch + 1) * 32;
            ra[0] = val0 ? *(const float4*)(Arow0 + kn) : make_float4(0, 0, 0, 0);
            ra[1] = val1 ? *(const float4*)(Arow1 + kn) : make_float4(0, 0, 0, 0);
            rbh[0] = *(const uint4*)(B0h + kn); rbh[1] = *(const uint4*)(B1h + kn);
            rbl[0] = *(const uint4*)(B0l + kn); rbl[1] = *(const uint4*)(B1l + kn);
        }
        uint32_t stA = (uint32_t)(ch & 1) * 20480;
        uint32_t stB = 40960 + (uint32_t)(ch & 1) * 40960;
#pragma unroll
        for (int ks = 0; ks < 2; ks++) {
            int kc = ks * 16;
            uint32_t ah[2][4], al[2][4];
#pragma unroll
            for (int mt = 0; mt < 2; mt++) {
                int r = warp_m * 32 + mt * 16 + (lane & 15);
                uint32_t off = (uint32_t)(r * LDS + kc + ((lane >> 4) << 3)) * 2;
                ldm_x4(ah[mt], sb + stA + off);
                ldm_x4(al[mt], sb + stA + 10240 + off);
            }
#pragma unroll
            for (int p = 0; p < 4; p++) {
                uint32_t off = bpair_off(warp_n * 64, p, kc, lane, LDS);
                uint32_t bh[4], bl[4];
                ldm_x4(bh, sb + stB + off);
                ldm_x4(bl, sb + stB + 20480 + off);
#pragma unroll
                for (int half = 0; half < 2; half++) {
                    int nt = p * 2 + half;
#pragma unroll
                    for (int mt = 0; mt < 2; mt++) {
                        mma_bf16(c[mt][nt], ah[mt], bh + half * 2);
                        mma_bf16(c[mt][nt], al[mt], bh + half * 2);
                        mma_bf16(c[mt][nt], ah[mt], bl + half * 2);
                    }
                }
            }
        }
        if (ch + 1 < NCH) {
            int kn = (ch + 1) * 32;
            uint32_t nsA = (uint32_t)((ch + 1) & 1) * 20480;
            uint32_t nsB = 40960 + (uint32_t)((ch + 1) & 1) * 40960;
            float4 s = *(const float4*)&sBnA[kn + qa * 4];
            float4 h = *(const float4*)&sBnC[kn + qa * 4];
#pragma unroll
            for (int it = 0; it < 2; it++) {
                float4 v;
                v.x = fmaxf(fmaf(ra[it].x, s.x, h.x), 0.f);
                v.y = fmaxf(fmaf(ra[it].y, s.y, h.y), 0.f);
                v.z = fmaxf(fmaf(ra[it].z, s.z, h.z), 0.f);
                v.w = fmaxf(fmaf(ra[it].w, s.w, h.w), 0.f);
                if (!(it ? val1 : val0)) v = make_float4(0, 0, 0, 0);
                uint32_t h01, l01, h23, l23;
                split_pack(v.x, v.y, h01, l01);
                split_pack(v.z, v.w, h23, l23);
                int r = ra0 + it * 64;
                *(uint2*)(smem + nsA + (r * LDS + qa * 4) * 2) = make_uint2(h01, h23);
                *(uint2*)(smem + nsA + 10240 + (r * LDS + qa * 4) * 2) = make_uint2(l01, l23);
            }
#pragma unroll
            for (int it = 0; it < 2; it++) {
                int n = nb0 + it * 128;
                *(uint4*)(smem + nsB + (n * LDS + qb * 8) * 2) = rbh[it];
                *(uint4*)(smem + nsB + 20480 + (n * LDS + qb * 8) * 2) = rbl[it];
            }
        }
    }

    int colb = warp_n * 64 + ((lane & 3) << 1);
    int rb = row0 + warp_m * 32 + (lane >> 2);
#pragma unroll
    for (int mt = 0; mt < 2; mt++) {
        int gr = rb + mt * 16;
#pragma unroll
        for (int nt = 0; nt < 8; nt++) {
            int col = colb + nt * 8;
            if (gr < NN)
                *(float2*)(out + (size_t)gr * HH + col) = make_float2(c[mt][nt][0], c[mt][nt][1]);
            if (gr + 8 < NN)
                *(float2*)(out + (size_t)(gr + 8) * HH + col) = make_float2(c[mt][nt][2], c[mt][nt][3]);
        }
    }
#pragma unroll
    for (int nt = 0; nt < 8; nt++) {
        float s0 = c[0][nt][0] + c[0][nt][2] + c[1][nt][0] + c[1][nt][2];
        float s1 = c[0][nt][1] + c[0][nt][3] + c[1][nt][1] + c[1][nt][3];
        float q0 = c[0][nt][0] * c[0][nt][0] + c[0][nt][2] * c[0][nt][2] +
                   c[1][nt][0] * c[1][nt][0] + c[1][nt][2] * c[1][nt][2];
        float q1 = c[0][nt][1] * c[0][nt][1] + c[0][nt][3] * c[0][nt][3] +
                   c[1][nt][1] * c[1][nt][1] + c[1][nt][3] * c[1][nt][3];
#pragma unroll
        for (int m = 4; m < 32; m <<= 1) {
            s0 += __shfl_xor_sync(0xffffffffu, s0, m);
            s1 += __shfl_xor_sync(0xffffffffu, s1, m);
            q0 += __shfl_xor_sync(0xffffffffu, q0, m);
            q1 += __shfl_xor_sync(0xffffffffu, q1, m);
        }
        if (lane < 4) {
            int col = warp_n * 64 + nt * 8 + lane * 2;
            atomicAdd(&statsOut[col], s0);
            atomicAdd(&statsOut[col + 1], s1);
            atomicAdd(&statsOut[HH + col], q0);
            atomicAdd(&statsOut[HH + col + 1], q1);
        }
    }
}

// ---------------- GEMM3 (K=256, N=40): 512 threads, low-reg, double-buffered -
// 16 warps: warp_m=wid&3 (32 rows), warp_n=wid>>2 (16 cols: two n8 tiles).
// smem: A stage s: hi s*20480, lo +10240; B stage s: hi 40960+s*10240, lo +5120;
// bnA 61440, bnC 62464. Total 63488.
__global__ __launch_bounds__(512, 1) void k_mma3(
    const float* __restrict__ A,
    const __nv_bfloat16* __restrict__ Bhi, const __nv_bfloat16* __restrict__ Blo,
    const float* __restrict__ stats, const float* __restrict__ gamma,
    const float* __restrict__ beta,
    const float* __restrict__ bias, float* __restrict__ out)
{
    constexpr int KDIM = 256, LDS = 40;
    extern __shared__ __align__(16) char smem[];
    float* sBnA = (float*)(smem + 61440);
    float* sBnC = (float*)(smem + 62464);

    int tid = threadIdx.x, lane = tid & 31, wid = tid >> 5;
    int warp_m = wid & 3, warp_n = wid >> 2;
    int row0 = blockIdx.x * 128;

    if (tid < HH) {
        float inv = 1.0f / (float)NN;
        float mean = stats[tid] * inv;
        float var = stats[HH + tid] * inv - mean * mean;
        float rstd = rsqrtf(var + BNEPS);
        float a = gamma[tid] * rstd;
        sBnA[tid] = a;
        sBnC[tid] = beta[tid] - a * mean;
    }

    float c[2][2][4];
#pragma unroll
    for (int mt = 0; mt < 2; mt++)
#pragma unroll
        for (int nt = 0; nt < 2; nt++)
#pragma unroll
            for (int q = 0; q < 4; q++) c[mt][nt][q] = 0.0f;

    uint32_t sb = smem_u32(smem);
    const int NCH = KDIM / 32;
    int qa = tid & 7, ra0 = tid >> 3;
    bool val0 = (row0 + ra0) < NN;
    bool val1 = (row0 + ra0 + 64) < NN;
    const float* Arow0 = A + (size_t)(row0 + ra0) * KDIM + qa * 4;
    const float* Arow1 = Arow0 + (size_t)64 * KDIM;
    // B: 512 threads, half store hi, half store lo (64 rows x 4 uint4 per split)
    int bhalf = tid >> 8;                // 0: hi, 1: lo
    int bidx = tid & 255;
    int nb = bidx >> 2, qb = bidx & 3;
    const __nv_bfloat16* Bp = (bhalf ? Blo : Bhi) + (size_t)nb * KDIM + qb * 8;

    float4 ra[2];
    uint4 rb;
    ra[0] = val0 ? *(const float4*)(Arow0) : make_float4(0, 0, 0, 0);
    ra[1] = val1 ? *(const float4*)(Arow1) : make_float4(0, 0, 0, 0);
    rb = *(const uint4*)(Bp);

    __syncthreads();   // bn tables ready

    {
        float4 s = *(const float4*)&sBnA[qa * 4];
        float4 h = *(const float4*)&sBnC[qa * 4];
#pragma unroll
        for (int it = 0; it < 2; it++) {
            float4 v;
            v.x = fmaxf(fmaf(ra[it].x, s.x, h.x), 0.f);
            v.y = fmaxf(fmaf(ra[it].y, s.y, h.y), 0.f);
            v.z = fmaxf(fmaf(ra[it].z, s.z, h.z), 0.f);
            v.w = fmaxf(fmaf(ra[it].w, s.w, h.w), 0.f);
            if (!(it ? val1 : val0)) v = make_float4(0, 0, 0, 0);
            uint32_t h01, l01, h23, l23;
            split_pack(v.x, v.y, h01, l01);
            split_pack(v.z, v.w, h23, l23);
            int r = ra0 + it * 64;
            *(uint2*)(smem + (r * LDS + qa * 4) * 2) = make_uint2(h01, h23);
            *(uint2*)(smem + 10240 + (r * LDS + qa * 4) * 2) = make_uint2(l01, l23);
        }
        *(uint4*)(smem + 40960 + bhalf * 5120 + (nb * LDS + qb * 8) * 2) = rb;
    }

#pragma unroll 1
    for (int ch = 0; ch < NCH; ch++) {
        __syncthreads();
        if (ch + 1 < NCH) {
            int kn = (ch + 1) * 32;
            ra[0] = val0 ? *(const float4*)(Arow0 + kn) : make_float4(0, 0, 0, 0);
            ra[1] = val1 ? *(const float4*)(Arow1 + kn) : make_float4(0, 0, 0, 0);
            rb = *(const uint4*)(Bp + kn);
        }
        uint32_t stA = (uint32_t)(ch & 1) * 20480;
        uint32_t stB = 40960 + (uint32_t)(ch & 1) * 10240;
#pragma unroll
        for (int ks = 0; ks < 2; ks++) {
            int kc = ks * 16;
            uint32_t bh[4], bl[4];
            uint32_t off = bpair_off(warp_n * 16, 0, kc, lane, LDS);
            ldm_x4(bh, sb + stB + off);
            ldm_x4(bl, sb + stB + 5120 + off);
#pragma unroll
            for (int mt = 0; mt < 2; mt++) {
                int r = warp_m * 32 + mt * 16 + (lane & 15);
                uint32_t aoff = (uint32_t)(r * LDS + kc + ((lane >> 4) << 3)) * 2;
                uint32_t ah[4], al[4];
                ldm_x4(ah, sb + stA + aoff);
                ldm_x4(al, sb + stA + 10240 + aoff);
#pragma unroll
                for (int half = 0; half < 2; half++) {
                    mma_bf16(c[mt][half], ah, bh + half * 2);
                    mma_bf16(c[mt][half], al, bh + half * 2);
                    mma_bf16(c[mt][half], ah, bl + half * 2);
                }
            }
        }
        if (ch + 1 < NCH) {
            int kn = (ch + 1) * 32;
            uint32_t nsA = (uint32_t)((ch + 1) & 1) * 20480;
            uint32_t nsB = 40960 + (uint32_t)((ch + 1) & 1) * 10240;
            float4 s = *(const float4*)&sBnA[kn + qa * 4];
            float4 h = *(const float4*)&sBnC[kn + qa * 4];
#pragma unroll
            for (int it = 0; it < 2; it++) {
                float4 v;
                v.x = fmaxf(fmaf(ra[it].x, s.x, h.x), 0.f);
                v.y = fmaxf(fmaf(ra[it].y, s.y, h.y), 0.f);
                v.z = fmaxf(fmaf(ra[it].z, s.z, h.z), 0.f);
                v.w = fmaxf(fmaf(ra[it].w, s.w, h.w), 0.f);
                if (!(it ? val1 : val0)) v = make_float4(0, 0, 0, 0);
                uint32_t h01, l01, h23, l23;
                split_pack(v.x, v.y, h01, l01);
                split_pack(v.z, v.w, h23, l23);
                int r = ra0 + it * 64;
                *(uint2*)(smem + nsA + (r * LDS + qa * 4) * 2) = make_uint2(h01, h23);
                *(uint2*)(smem + nsA + 10240 + (r * LDS + qa * 4) * 2) = make_uint2(l01, l23);
            }
            *(uint4*)(smem + nsB + bhalf * 5120 + (nb * LDS + qb * 8) * 2) = rb;
        }
    }

    int colbase = warp_n * 16 + ((lane & 3) << 1);
    int rbase = row0 + warp_m * 32 + (lane >> 2);
#pragma unroll
    for (int mt = 0; mt < 2; mt++) {
        int r0g = rbase + mt * 16;
#pragma unroll
        for (int nt = 0; nt < 2; nt++) {
            int col = colbase + nt * 8;
            if (col >= CC) continue;
            float bx = bias[col], by = bias[col + 1];
            if (r0g < NN)
                *(float2*)(out + (size_t)r0g * CC + col) =
                    make_float2(c[mt][nt][0] + bx, c[mt][nt][1] + by);
            if (r0g + 8 < NN)
                *(float2*)(out + (size_t)(r0g + 8) * CC + col) =
                    make_float2(c[mt][nt][2] + bx, c[mt][nt][3] + by);
        }
    }
}

// ---------------- launch ----------------
extern "C" void kernel_launch(void* const* d_in, const int* in_sizes, int n_in,
                              void* d_out, int out_size) {
    const float* feat = (const float*)d_in[0];
    const int*   src  = (const int*)d_in[1];
    const int*   dst  = (const int*)d_in[2];
    const float* W1   = (const float*)d_in[3];
    const float* g1   = (const float*)d_in[5];
    const float* be1  = (const float*)d_in[6];
    const float* W2   = (const float*)d_in[7];
    const float* g2   = (const float*)d_in[9];
    const float* be2  = (const float*)d_in[10];
    const float* W3   = (const float*)d_in[11];
    const float* b3   = (const float*)d_in[12];
    float* out = (float*)d_out;

    float *p_z1, *p_z2, *p_z3, *p_z4, *p_y1, *p_y2, *p_stats;
    __nv_bfloat16 *p_w1h, *p_w1l, *p_w2h, *p_w2l, *p_w3h, *p_w3l;
    cudaGetSymbolAddress((void**)&p_z1, g_z1);
    cudaGetSymbolAddress((void**)&p_z2, g_z2);
    cudaGetSymbolAddress((void**)&p_z3, g_z3);
    cudaGetSymbolAddress((void**)&p_z4, g_z4);
    cudaGetSymbolAddress((void**)&p_y1, g_y1);
    cudaGetSymbolAddress((void**)&p_y2, g_y2);
    cudaGetSymbolAddress((void**)&p_stats, g_stats);
    cudaGetSymbolAddress((void**)&p_w1h, g_w1h);
    cudaGetSymbolAddress((void**)&p_w1l, g_w1l);
    cudaGetSymbolAddress((void**)&p_w2h, g_w2h);
    cudaGetSymbolAddress((void**)&p_w2l, g_w2l);
    cudaGetSymbolAddress((void**)&p_w3h, g_w3h);
    cudaGetSymbolAddress((void**)&p_w3l, g_w3l);

    const int SM1 = 61440;
    const int SM2 = 124928;
    const int SM3 = 63488;
    cudaFuncSetAttribute((const void*)k_mma1,
                         cudaFuncAttributeMaxDynamicSharedMemorySize, SM1);
    cudaFuncSetAttribute((const void*)k_mma2,
                         cudaFuncAttributeMaxDynamicSharedMemorySize, SM2);
    cudaFuncSetAttribute((const void*)k_mma3,
                         cudaFuncAttributeMaxDynamicSharedMemorySize, SM3);

    // CSR build (weight split fused into count)
    k_count<<<(EE + 255) / 256, 256>>>(dst, W1, W2, W3);
    k_scan1<<<NB_SCAN, 1024>>>();
    k_scan3<<<NB_SCAN, 1024>>>();
    k_fill<<<(EE + 255) / 256, 256>>>(src, dst);

    // propagation
    int gblocks = (NN * 32 + 255) / 256;
    k_gather<1><<<gblocks, 256>>>(feat, p_z1);
    k_gather<0><<<gblocks, 256>>>(p_z1, p_z2);
    k_gather<0><<<gblocks, 256>>>(p_z2, p_z3);
    k_gather<0><<<gblocks, 256>>>(p_z3, p_z4);

    int mgrid = (NN + 127) / 128;
    k_mma1<<<mgrid, 512, SM1>>>(p_z1, p_z2, p_z3, p_z4, feat,
                                p_w1h, p_w1l, p_y1, p_stats);
    k_mma2<<<mgrid, 512, SM2>>>(p_y1, p_w2h, p_w2l,
                                p_stats, g1, be1, p_y2, p_stats + 2 * HH);
    k_mma3<<<mgrid, 512, SM3>>>(p_y2, p_w3h, p_w3l,
                                p_stats + 2 * HH, g2, be2, b3, out);
}

// round 13
// speedup vs baseline: 1.0655x; 1.0367x over previous
#include <cuda_runtime.h>
#include <cuda_bf16.h>
#include <math.h>
#include <stdint.h>

#define NN 100000
#define EE 1250000
#define DD 64
#define HH 256
#define CC 40
#define BNEPS 1e-5f
#define NB_SCAN 98

// ---------------- device scratch ----------------
__device__ float g_z1[NN * DD];
__device__ float g_z2[NN * DD];
__device__ float g_z3[NN * DD];
__device__ float g_z4[NN * DD];
__device__ float g_norm[NN];
__device__ float g_sdeg[NN];
__device__ int   g_deg[NN];       // zero at load; re-zeroed by k_gather<1> each call
__device__ int   g_off[NN + 1];
__device__ int   g_cursor[NN];
__device__ int   g_csr[EE];
__device__ int   g_bsum[NB_SCAN];
__device__ float g_y1[NN * HH];
__device__ float g_y2[NN * HH];
__device__ float g_stats[4 * HH]; // zero at load; re-zeroed by k_gather<1> each call
__device__ __nv_bfloat16 g_w1h[HH * DD], g_w1l[HH * DD];
__device__ __nv_bfloat16 g_w2h[HH * HH], g_w2l[HH * HH];
__device__ __nv_bfloat16 g_w3h[64 * HH], g_w3l[64 * HH];

// ---------------- helpers ----------------
__device__ __forceinline__ uint32_t smem_u32(const void* p) {
    uint32_t a;
    asm("{ .reg .u64 t; cvta.to.shared.u64 t, %1; cvt.u32.u64 %0, t; }" : "=r"(a) : "l"(p));
    return a;
}
__device__ __forceinline__ void ldm_x4(uint32_t* r, uint32_t addr) {
    asm volatile("ldmatrix.sync.aligned.m8n8.x4.shared.b16 {%0,%1,%2,%3}, [%4];"
                 : "=r"(r[0]), "=r"(r[1]), "=r"(r[2]), "=r"(r[3]) : "r"(addr));
}
__device__ __forceinline__ void ldm_x2(uint32_t* r, uint32_t addr) {
    asm volatile("ldmatrix.sync.aligned.m8n8.x2.shared.b16 {%0,%1}, [%2];"
                 : "=r"(r[0]), "=r"(r[1]) : "r"(addr));
}
__device__ __forceinline__ void mma_bf16(float* c, const uint32_t* a, const uint32_t* b) {
    asm volatile(
        "mma.sync.aligned.m16n8k16.row.col.f32.bf16.bf16.f32 "
        "{%0,%1,%2,%3}, {%4,%5,%6,%7}, {%8,%9}, {%0,%1,%2,%3};"
        : "+f"(c[0]), "+f"(c[1]), "+f"(c[2]), "+f"(c[3])
        : "r"(a[0]), "r"(a[1]), "r"(a[2]), "r"(a[3]), "r"(b[0]), "r"(b[1]));
}
__device__ __forceinline__ void split_pack(float x, float y, uint32_t& hi, uint32_t& lo) {
    uint32_t h;
    asm("cvt.rn.bf16x2.f32 %0, %1, %2;" : "=r"(h) : "f"(y), "f"(x));
    float xb = __uint_as_float(h << 16);
    float yb = __uint_as_float(h & 0xffff0000u);
    float rx = x - xb, ry = y - yb;
    uint32_t l;
    asm("cvt.rn.bf16x2.f32 %0, %1, %2;" : "=r"(l) : "f"(ry), "f"(rx));
    hi = h;
    lo = l;
}
__device__ __forceinline__ void wsplit(const float* W, __nv_bfloat16* hi, __nv_bfloat16* lo,
                                       int idx, int K, int Nsrc) {
    int n = idx / K, k = idx - n * K;
    float v = (n < Nsrc) ? W[(size_t)k * Nsrc + n] : 0.0f;
    __nv_bfloat16 h = __float2bfloat16(v);
    hi[idx] = h;
    lo[idx] = __float2bfloat16(v - __bfloat162float(h));
}

// ---------------- count (+ fused weight split) ----------------
__global__ void k_count(const int* __restrict__ dst, const float* __restrict__ W1,
                        const float* __restrict__ W2, const float* __restrict__ W3) {
    int e = blockIdx.x * blockDim.x + threadIdx.x;
    if (e < EE) atomicAdd(&g_deg[dst[e]], 1);
    if (e < HH * DD) wsplit(W1, g_w1h, g_w1l, e, DD, HH);
    else if (e < HH * DD + HH * HH) wsplit(W2, g_w2h, g_w2l, e - HH * DD, HH, HH);
    else if (e < HH * DD + HH * HH + 64 * HH)
        wsplit(W3, g_w3h, g_w3l, e - HH * DD - HH * HH, HH, CC);
}
__global__ void k_scan1() {
    __shared__ int s[1024];
    int t = threadIdx.x;
    int i = blockIdx.x * 1024 + t;
    int v = (i < NN) ? g_deg[i] : 0;
    s[t] = v;
    __syncthreads();
    for (int off = 1; off < 1024; off <<= 1) {
        int x = (t >= off) ? s[t - off] : 0;
        __syncthreads();
        s[t] += x;
        __syncthreads();
    }
    if (i < NN) g_off[i] = s[t] - v;
    if (t == 1023) g_bsum[blockIdx.x] = s[1023];
}
__global__ void k_scan3() {
    __shared__ int sb[128];
    int t = threadIdx.x;
    if (t < 128) sb[t] = (t < NB_SCAN) ? g_bsum[t] : 0;
    __syncthreads();
    for (int off = 1; off < 128; off <<= 1) {
        int x = 0;
        if (t < 128 && t >= off) x = sb[t - off];
        __syncthreads();
        if (t < 128) sb[t] += x;
        __syncthreads();
    }
    int base = (blockIdx.x > 0) ? sb[blockIdx.x - 1] : 0;
    int i = blockIdx.x * 1024 + t;
    if (i < NN) {
        int off = g_off[i] + base;
        g_off[i] = off;
        g_cursor[i] = off;
        int d = g_deg[i];
        int dc = (d > 0) ? d : 1;
        g_norm[i] = rsqrtf((float)dc);
        g_sdeg[i] = sqrtf((float)dc);
    }
    if (i == NN) g_off[NN] = EE;
}
__global__ void k_fill(const int* __restrict__ src, const int* __restrict__ dst) {
    int e = blockIdx.x * blockDim.x + threadIdx.x;
    if (e < EE) {
        int p = atomicAdd(&g_cursor[dst[e]], 1);
        g_csr[p] = src[e];
    }
}

// ---------------- propagation ----------------
template <int FIRST>
__global__ __launch_bounds__(256) void k_gather(const float* __restrict__ zin,
                                                float* __restrict__ zout) {
    if (FIRST) {
        int gid = blockIdx.x * blockDim.x + threadIdx.x;
        if (gid < NN) g_deg[gid] = 0;
        if (gid < 4 * HH) g_stats[gid] = 0.0f;
    }
    int warp = (blockIdx.x * blockDim.x + threadIdx.x) >> 5;
    int lane = threadIdx.x & 31;
    if (warp >= NN) return;
    int beg = g_off[warp], end = g_off[warp + 1];
    int grp = lane >> 4, sub = lane & 15;
    const float4* z4 = (const float4*)zin;
    float4 a = make_float4(0.f, 0.f, 0.f, 0.f);
    float4 b = make_float4(0.f, 0.f, 0.f, 0.f);
    int e = beg + grp;
    for (; e + 2 < end; e += 4) {
        int j0 = g_csr[e], j1 = g_csr[e + 2];
        float4 v0 = z4[j0 * 16 + sub];
        float4 v1 = z4[j1 * 16 + sub];
        if (FIRST) {
            float n0 = g_norm[j0], n1 = g_norm[j1];
            a.x = fmaf(n0, v0.x, a.x); a.y = fmaf(n0, v0.y, a.y);
            a.z = fmaf(n0, v0.z, a.z); a.w = fmaf(n0, v0.w, a.w);
            b.x = fmaf(n1, v1.x, b.x); b.y = fmaf(n1, v1.y, b.y);
            b.z = fmaf(n1, v1.z, b.z); b.w = fmaf(n1, v1.w, b.w);
        } else {
            a.x += v0.x; a.y += v0.y; a.z += v0.z; a.w += v0.w;
            b.x += v1.x; b.y += v1.y; b.z += v1.z; b.w += v1.w;
        }
    }
    if (e < end) {
        int j = g_csr[e];
        float4 v = z4[j * 16 + sub];
        if (FIRST) {
            float nj = g_norm[j];
            a.x = fmaf(nj, v.x, a.x); a.y = fmaf(nj, v.y, a.y);
            a.z = fmaf(nj, v.z, a.z); a.w = fmaf(nj, v.w, a.w);
        } else {
            a.x += v.x; a.y += v.y; a.z += v.z; a.w += v.w;
        }
    }
    a.x += b.x; a.y += b.y; a.z += b.z; a.w += b.w;
    a.x += __shfl_xor_sync(0xffffffffu, a.x, 16);
    a.y += __shfl_xor_sync(0xffffffffu, a.y, 16);
    a.z += __shfl_xor_sync(0xffffffffu, a.z, 16);
    a.w += __shfl_xor_sync(0xffffffffu, a.w, 16);
    if (grp == 0) {
        float ni = g_norm[warp];
        float n2 = ni * ni;
        ((float4*)zout)[warp * 16 + sub] =
            make_float4(n2 * a.x, n2 * a.y, n2 * a.z, n2 * a.w);
    }
}

// B paired-fragment address
__device__ __forceinline__ uint32_t bpair_off(int warpN, int p, int kc, int lane, int LDS) {
    int r = warpN + p * 16 + (lane & 7) + ((lane & 16) >> 1);
    int col = kc + (((lane & 15) >> 3) << 3);
    return (uint32_t)(r * LDS + col) * 2;
}

// ---------------- GEMM1: 128x256, K=64 (single-stage) -----------------------
__global__ __launch_bounds__(512, 1) void k_mma1(
    const float* __restrict__ Z1, const float* __restrict__ Z2,
    const float* __restrict__ Z3, const float* __restrict__ Z4,
    const float* __restrict__ feat,
    const __nv_bfloat16* __restrict__ Bhi, const __nv_bfloat16* __restrict__ Blo,
    float* __restrict__ out, float* __restrict__ stats)
{
    constexpr int KDIM = DD, LDS = 40;
    extern __shared__ __align__(16) char smem[];
    __nv_bfloat16* sAhi = (__nv_bfloat16*)(smem);
    __nv_bfloat16* sAlo = (__nv_bfloat16*)(smem + 10240);
    __nv_bfloat16* sBhi = (__nv_bfloat16*)(smem + 20480);
    __nv_bfloat16* sBlo = (__nv_bfloat16*)(smem + 40960);

    int tid = threadIdx.x, lane = tid & 31, wid = tid >> 5;
    int warp_m = wid & 3, warp_n = wid >> 2;
    int row0 = blockIdx.x * 128;

    float c[2][8][4];
#pragma unroll
    for (int mt = 0; mt < 2; mt++)
#pragma unroll
        for (int nt = 0; nt < 8; nt++)
#pragma unroll
            for (int q = 0; q < 4; q++) c[mt][nt][q] = 0.0f;

    uint32_t aAhi = smem_u32(sAhi), aAlo = smem_u32(sAlo);
    uint32_t aBhi = smem_u32(sBhi), aBlo = smem_u32(sBlo);

    int qa = tid & 7, ra0 = tid >> 3;
    int qb = tid & 3, nb0 = tid >> 2;
    bool val0 = (row0 + ra0) < NN;
    bool val1 = (row0 + ra0 + 64) < NN;
    float sd0 = val0 ? (0.2375f * g_sdeg[row0 + ra0]) : 0.f;
    float sd1 = val1 ? (0.2375f * g_sdeg[row0 + ra0 + 64]) : 0.f;

#pragma unroll 1
    for (int ch = 0; ch < KDIM / 32; ch++) {
        int k0 = ch * 32;
#pragma unroll
        for (int it = 0; it < 2; it++) {
            int r = ra0 + it * 64;
            bool valid = it ? val1 : val0;
            float sd = it ? sd1 : sd0;
            float4 v = make_float4(0, 0, 0, 0);
            if (valid) {
                size_t o = (size_t)(row0 + r) * KDIM + k0 + qa * 4;
                float4 z1 = *(const float4*)(Z1 + o);
                float4 z2 = *(const float4*)(Z2 + o);
                float4 z3 = *(const float4*)(Z3 + o);
                float4 z4 = *(const float4*)(Z4 + o);
                float4 f = *(const float4*)(feat + o);
                v.x = sd * (z1.x + z2.x + z3.x + z4.x) + 0.05f * f.x;
                v.y = sd * (z1.y + z2.y + z3.y + z4.y) + 0.05f * f.y;
                v.z = sd * (z1.z + z2.z + z3.z + z4.z) + 0.05f * f.z;
                v.w = sd * (z1.w + z2.w + z3.w + z4.w) + 0.05f * f.w;
            }
            uint32_t h01, l01, h23, l23;
            split_pack(v.x, v.y, h01, l01);
            split_pack(v.z, v.w, h23, l23);
            *(uint2*)&sAhi[r * LDS + qa * 4] = make_uint2(h01, h23);
            *(uint2*)&sAlo[r * LDS + qa * 4] = make_uint2(l01, l23);
        }
#pragma unroll
        for (int it = 0; it < 2; it++) {
            int n = nb0 + it * 128;
            size_t goff = (size_t)n * KDIM + k0 + qb * 8;
            *(uint4*)&sBhi[n * LDS + qb * 8] = *(const uint4*)(Bhi + goff);
            *(uint4*)&sBlo[n * LDS + qb * 8] = *(const uint4*)(Blo + goff);
        }
        __syncthreads();
#pragma unroll
        for (int ks = 0; ks < 2; ks++) {
            int kc = ks * 16;
            uint32_t ah[2][4], al[2][4];
#pragma unroll
            for (int mt = 0; mt < 2; mt++) {
                int r = warp_m * 32 + mt * 16 + (lane & 15);
                uint32_t off = (uint32_t)(r * LDS + kc + ((lane >> 4) << 3)) * 2;
                ldm_x4(ah[mt], aAhi + off);
                ldm_x4(al[mt], aAlo + off);
            }
#pragma unroll
            for (int p = 0; p < 4; p++) {
                uint32_t off = bpair_off(warp_n * 64, p, kc, lane, LDS);
                uint32_t bh[4], bl[4];
                ldm_x4(bh, aBhi + off);
                ldm_x4(bl, aBlo + off);
#pragma unroll
                for (int half = 0; half < 2; half++) {
                    int nt = p * 2 + half;
#pragma unroll
                    for (int mt = 0; mt < 2; mt++) {
                        mma_bf16(c[mt][nt], ah[mt], bh + half * 2);
                        mma_bf16(c[mt][nt], al[mt], bh + half * 2);
                        mma_bf16(c[mt][nt], ah[mt], bl + half * 2);
                    }
                }
            }
        }
        __syncthreads();
    }
    int colb = warp_n * 64 + ((lane & 3) << 1);
    int rb = row0 + warp_m * 32 + (lane >> 2);
#pragma unroll
    for (int mt = 0; mt < 2; mt++) {
        int gr = rb + mt * 16;
#pragma unroll
        for (int nt = 0; nt < 8; nt++) {
            int col = colb + nt * 8;
            if (gr < NN)
                *(float2*)(out + (size_t)gr * HH + col) = make_float2(c[mt][nt][0], c[mt][nt][1]);
            if (gr + 8 < NN)
                *(float2*)(out + (size_t)(gr + 8) * HH + col) = make_float2(c[mt][nt][2], c[mt][nt][3]);
        }
    }
#pragma unroll
    for (int nt = 0; nt < 8; nt++) {
        float s0 = c[0][nt][0] + c[0][nt][2] + c[1][nt][0] + c[1][nt][2];
        float s1 = c[0][nt][1] + c[0][nt][3] + c[1][nt][1] + c[1][nt][3];
        float q0 = c[0][nt][0] * c[0][nt][0] + c[0][nt][2] * c[0][nt][2] +
                   c[1][nt][0] * c[1][nt][0] + c[1][nt][2] * c[1][nt][2];
        float q1 = c[0][nt][1] * c[0][nt][1] + c[0][nt][3] * c[0][nt][3] +
                   c[1][nt][1] * c[1][nt][1] + c[1][nt][3] * c[1][nt][3];
#pragma unroll
        for (int m = 4; m < 32; m <<= 1) {
            s0 += __shfl_xor_sync(0xffffffffu, s0, m);
            s1 += __shfl_xor_sync(0xffffffffu, s1, m);
            q0 += __shfl_xor_sync(0xffffffffu, q0, m);
            q1 += __shfl_xor_sync(0xffffffffu, q1, m);
        }
        if (lane < 4) {
            int col = warp_n * 64 + nt * 8 + lane * 2;
            atomicAdd(&stats[col], s0);
            atomicAdd(&stats[col + 1], s1);
            atomicAdd(&stats[HH + col], q0);
            atomicAdd(&stats[HH + col + 1], q1);
        }
    }
}

// ---------------- GEMM2: 128x256, K=256; double-buffered, fused BN prologue --
__global__ __launch_bounds__(512, 1) void k_mma2(
    const float* __restrict__ A,
    const __nv_bfloat16* __restrict__ Bhi, const __nv_bfloat16* __restrict__ Blo,
    const float* __restrict__ stats, const float* __restrict__ gamma,
    const float* __restrict__ beta,
    float* __restrict__ out, float* __restrict__ statsOut)
{
    constexpr int KDIM = HH, LDS = 40;
    extern __shared__ __align__(16) char smem[];
    float* sBnA = (float*)(smem + 122880);
    float* sBnC = (float*)(smem + 123904);

    int tid = threadIdx.x, lane = tid & 31, wid = tid >> 5;
    int warp_m = wid & 3, warp_n = wid >> 2;
    int row0 = blockIdx.x * 128;

    if (tid < HH) {
        float inv = 1.0f / (float)NN;
        float mean = stats[tid] * inv;
        float var = stats[HH + tid] * inv - mean * mean;
        float rstd = rsqrtf(var + BNEPS);
        float a = gamma[tid] * rstd;
        sBnA[tid] = a;
        sBnC[tid] = beta[tid] - a * mean;
    }

    float c[2][8][4];
#pragma unroll
    for (int mt = 0; mt < 2; mt++)
#pragma unroll
        for (int nt = 0; nt < 8; nt++)
#pragma unroll
            for (int q = 0; q < 4; q++) c[mt][nt][q] = 0.0f;

    uint32_t sb = smem_u32(smem);
    int qa = tid & 7, ra0 = tid >> 3;
    int qb = tid & 3, nb0 = tid >> 2;
    bool val0 = (row0 + ra0) < NN;
    bool val1 = (row0 + ra0 + 64) < NN;
    const float* Arow0 = A + (size_t)(row0 + ra0) * KDIM + qa * 4;
    const float* Arow1 = Arow0 + (size_t)64 * KDIM;
    const __nv_bfloat16* B0h = Bhi + (size_t)nb0 * KDIM + qb * 8;
    const __nv_bfloat16* B1h = B0h + (size_t)128 * KDIM;
    const __nv_bfloat16* B0l = Blo + (size_t)nb0 * KDIM + qb * 8;
    const __nv_bfloat16* B1l = B0l + (size_t)128 * KDIM;

    const int NCH = KDIM / 32;
    float4 ra[2];
    uint4 rbh[2], rbl[2];
    ra[0] = val0 ? *(const float4*)(Arow0) : make_float4(0, 0, 0, 0);
    ra[1] = val1 ? *(const float4*)(Arow1) : make_float4(0, 0, 0, 0);
    rbh[0] = *(const uint4*)(B0h); rbh[1] = *(const uint4*)(B1h);
    rbl[0] = *(const uint4*)(B0l); rbl[1] = *(const uint4*)(B1l);

    __syncthreads();

    {
        float4 s = *(const float4*)&sBnA[qa * 4];
        float4 h = *(const float4*)&sBnC[qa * 4];
#pragma unroll
        for (int it = 0; it < 2; it++) {
            float4 v;
            v.x = fmaxf(fmaf(ra[it].x, s.x, h.x), 0.f);
            v.y = fmaxf(fmaf(ra[it].y, s.y, h.y), 0.f);
            v.z = fmaxf(fmaf(ra[it].z, s.z, h.z), 0.f);
            v.w = fmaxf(fmaf(ra[it].w, s.w, h.w), 0.f);
            if (!(it ? val1 : val0)) v = make_float4(0, 0, 0, 0);
            uint32_t h01, l01, h23, l23;
            split_pack(v.x, v.y, h01, l01);
            split_pack(v.z, v.w, h23, l23);
            int r = ra0 + it * 64;
            *(uint2*)(smem + (r * LDS + qa * 4) * 2) = make_uint2(h01, h23);
            *(uint2*)(smem + 10240 + (r * LDS + qa * 4) * 2) = make_uint2(l01, l23);
        }
#pragma unroll
        for (int it = 0; it < 2; it++) {
            int n = nb0 + it * 128;
            *(uint4*)(smem + 40960 + (n * LDS + qb * 8) * 2) = rbh[it];
            *(uint4*)(smem + 40960 + 20480 + (n * LDS + qb * 8) * 2) = rbl[it];
        }
    }

#pragma unroll 1
    for (int ch = 0; ch < NCH; ch++) {
        __syncthreads();
        if (ch + 1 < NCH) {
            int kn = (ch + 1) * 32;
            ra[0] = val0 ? *(const float4*)(Arow0 + kn) : make_float4(0, 0, 0, 0);
            ra[1] = val1 ? *(const float4*)(Arow1 + kn) : make_float4(0, 0, 0, 0);
            rbh[0] = *(const uint4*)(B0h + kn); rbh[1] = *(const uint4*)(B1h + kn);
            rbl[0] = *(const uint4*)(B0l + kn); rbl[1] = *(const uint4*)(B1l + kn);
        }
        uint32_t stA = (uint32_t)(ch & 1) * 20480;
        uint32_t stB = 40960 + (uint32_t)(ch & 1) * 40960;
#pragma unroll
        for (int ks = 0; ks < 2; ks++) {
            int kc = ks * 16;
            uint32_t ah[2][4], al[2][4];
#pragma unroll
            for (int mt = 0; mt < 2; mt++) {
                int r = warp_m * 32 + mt * 16 + (lane & 15);
                uint32_t off = (uint32_t)(r * LDS + kc + ((lane >> 4) << 3)) * 2;
                ldm_x4(ah[mt], sb + stA + off);
                ldm_x4(al[mt], sb + stA + 10240 + off);
            }
#pragma unroll
            for (int p = 0; p < 4; p++) {
                uint32_t off = bpair_off(warp_n * 64, p, kc, lane, LDS);
                uint32_t bh[4], bl[4];
                ldm_x4(bh, sb + stB + off);
                ldm_x4(bl, sb + stB + 20480 + off);
#pragma unroll
                for (int half = 0; half < 2; half++) {
                    int nt = p * 2 + half;
#pragma unroll
                    for (int mt = 0; mt < 2; mt++) {
                        mma_bf16(c[mt][nt], ah[mt], bh + half * 2);
                        mma_bf16(c[mt][nt], al[mt], bh + half * 2);
                        mma_bf16(c[mt][nt], ah[mt], bl + half * 2);
                    }
                }
            }
        }
        if (ch + 1 < NCH) {
            int kn = (ch + 1) * 32;
            uint32_t nsA = (uint32_t)((ch + 1) & 1) * 20480;
            uint32_t nsB = 40960 + (uint32_t)((ch + 1) & 1) * 40960;
            float4 s = *(const float4*)&sBnA[kn + qa * 4];
            float4 h = *(const float4*)&sBnC[kn + qa * 4];
#pragma unroll
            for (int it = 0; it < 2; it++) {
                float4 v;
                v.x = fmaxf(fmaf(ra[it].x, s.x, h.x), 0.f);
                v.y = fmaxf(fmaf(ra[it].y, s.y, h.y), 0.f);
                v.z = fmaxf(fmaf(ra[it].z, s.z, h.z), 0.f);
                v.w = fmaxf(fmaf(ra[it].w, s.w, h.w), 0.f);
                if (!(it ? val1 : val0)) v = make_float4(0, 0, 0, 0);
                uint32_t h01, l01, h23, l23;
                split_pack(v.x, v.y, h01, l01);
                split_pack(v.z, v.w, h23, l23);
                int r = ra0 + it * 64;
                *(uint2*)(smem + nsA + (r * LDS + qa * 4) * 2) = make_uint2(h01, h23);
                *(uint2*)(smem + nsA + 10240 + (r * LDS + qa * 4) * 2) = make_uint2(l01, l23);
            }
#pragma unroll
            for (int it = 0; it < 2; it++) {
                int n = nb0 + it * 128;
                *(uint4*)(smem + nsB + (n * LDS + qb * 8) * 2) = rbh[it];
                *(uint4*)(smem + nsB + 20480 + (n * LDS + qb * 8) * 2) = rbl[it];
            }
        }
    }

    int colb = warp_n * 64 + ((lane & 3) << 1);
    int rb = row0 + warp_m * 32 + (lane >> 2);
#pragma unroll
    for (int mt = 0; mt < 2; mt++) {
        int gr = rb + mt * 16;
#pragma unroll
        for (int nt = 0; nt < 8; nt++) {
            int col = colb + nt * 8;
            if (gr < NN)
                *(float2*)(out + (size_t)gr * HH + col) = make_float2(c[mt][nt][0], c[mt][nt][1]);
            if (gr + 8 < NN)
                *(float2*)(out + (size_t)(gr + 8) * HH + col) = make_float2(c[mt][nt][2], c[mt][nt][3]);
        }
    }
#pragma unroll
    for (int nt = 0; nt < 8; nt++) {
        float s0 = c[0][nt][0] + c[0][nt][2] + c[1][nt][0] + c[1][nt][2];
        float s1 = c[0][nt][1] + c[0][nt][3] + c[1][nt][1] + c[1][nt][3];
        float q0 = c[0][nt][0] * c[0][nt][0] + c[0][nt][2] * c[0][nt][2] +
                   c[1][nt][0] * c[1][nt][0] + c[1][nt][2] * c[1][nt][2];
        float q1 = c[0][nt][1] * c[0][nt][1] + c[0][nt][3] * c[0][nt][3] +
                   c[1][nt][1] * c[1][nt][1] + c[1][nt][3] * c[1][nt][3];
#pragma unroll
        for (int m = 4; m < 32; m <<= 1) {
            s0 += __shfl_xor_sync(0xffffffffu, s0, m);
            s1 += __shfl_xor_sync(0xffffffffu, s1, m);
            q0 += __shfl_xor_sync(0xffffffffu, q0, m);
            q1 += __shfl_xor_sync(0xffffffffu, q1, m);
        }
        if (lane < 4) {
            int col = warp_n * 64 + nt * 8 + lane * 2;
            atomicAdd(&statsOut[col], s0);
            atomicAdd(&statsOut[col + 1], s1);
            atomicAdd(&statsOut[HH + col], q0);
            atomicAdd(&statsOut[HH + col + 1], q1);
        }
    }
}

// ---------------- GEMM3 (K=256): 256 threads, 128x48 effective tile ----------
// 8 warps: warp_m = wid&3 (32 rows), warp_n = wid>>2 (24 cols = 3 n8 tiles).
// Cols 40..47 computed vs zero-padded weights, never stored.
// smem: A stage s: hi s*20480, lo +10240; B stage s: hi 40960+s*10240, lo +5120;
// bnA 61440, bnC 62464. Total 63488.
__global__ __launch_bounds__(256) void k_mma3(
    const float* __restrict__ A,
    const __nv_bfloat16* __restrict__ Bhi, const __nv_bfloat16* __restrict__ Blo,
    const float* __restrict__ stats, const float* __restrict__ gamma,
    const float* __restrict__ beta,
    const float* __restrict__ bias, float* __restrict__ out)
{
    constexpr int KDIM = 256, LDS = 40;
    extern __shared__ __align__(16) char smem[];
    float* sBnA = (float*)(smem + 61440);
    float* sBnC = (float*)(smem + 62464);

    int tid = threadIdx.x, lane = tid & 31, wid = tid >> 5;
    int warp_m = wid & 3, warp_n = wid >> 2;
    int row0 = blockIdx.x * 128;

    if (tid < HH) {
        float inv = 1.0f / (float)NN;
        float mean = stats[tid] * inv;
        float var = stats[HH + tid] * inv - mean * mean;
        float rstd = rsqrtf(var + BNEPS);
        float a = gamma[tid] * rstd;
        sBnA[tid] = a;
        sBnC[tid] = beta[tid] - a * mean;
    }

    float c[2][3][4];
#pragma unroll
    for (int mt = 0; mt < 2; mt++)
#pragma unroll
        for (int nt = 0; nt < 3; nt++)
#pragma unroll
            for (int q = 0; q < 4; q++) c[mt][nt][q] = 0.0f;

    uint32_t sb = smem_u32(smem);
    const int NCH = KDIM / 32;
    int qa = tid & 7;
    int rA[4]; bool vA[4];
#pragma unroll
    for (int it = 0; it < 4; it++) {
        rA[it] = (tid + it * 256) >> 3;
        vA[it] = (row0 + rA[it]) < NN;
    }
    int nb = tid >> 2, qb = tid & 3;

    float4 ra[4];
    uint4 rbh, rbl;
#pragma unroll
    for (int it = 0; it < 4; it++)
        ra[it] = vA[it] ? *(const float4*)(A + (size_t)(row0 + rA[it]) * KDIM + qa * 4)
                        : make_float4(0, 0, 0, 0);
    rbh = *(const uint4*)(Bhi + (size_t)nb * KDIM + qb * 8);
    rbl = *(const uint4*)(Blo + (size_t)nb * KDIM + qb * 8);

    __syncthreads();

    {
        float4 s = *(const float4*)&sBnA[qa * 4];
        float4 h = *(const float4*)&sBnC[qa * 4];
#pragma unroll
        for (int it = 0; it < 4; it++) {
            float4 v;
            v.x = fmaxf(fmaf(ra[it].x, s.x, h.x), 0.f);
            v.y = fmaxf(fmaf(ra[it].y, s.y, h.y), 0.f);
            v.z = fmaxf(fmaf(ra[it].z, s.z, h.z), 0.f);
            v.w = fmaxf(fmaf(ra[it].w, s.w, h.w), 0.f);
            if (!vA[it]) v = make_float4(0, 0, 0, 0);
            uint32_t h01, l01, h23, l23;
            split_pack(v.x, v.y, h01, l01);
            split_pack(v.z, v.w, h23, l23);
            *(uint2*)(smem + (rA[it] * LDS + qa * 4) * 2) = make_uint2(h01, h23);
            *(uint2*)(smem + 10240 + (rA[it] * LDS + qa * 4) * 2) = make_uint2(l01, l23);
        }
        *(uint4*)(smem + 40960 + (nb * LDS + qb * 8) * 2) = rbh;
        *(uint4*)(smem + 40960 + 5120 + (nb * LDS + qb * 8) * 2) = rbl;
    }

#pragma unroll 1
    for (int ch = 0; ch < NCH; ch++) {
        __syncthreads();
        if (ch + 1 < NCH) {
            int kn = (ch + 1) * 32;
#pragma unroll
            for (int it = 0; it < 4; it++)
                ra[it] = vA[it] ? *(const float4*)(A + (size_t)(row0 + rA[it]) * KDIM + kn + qa * 4)
                                : make_float4(0, 0, 0, 0);
            rbh = *(const uint4*)(Bhi + (size_t)nb * KDIM + kn + qb * 8);
            rbl = *(const uint4*)(Blo + (size_t)nb * KDIM + kn + qb * 8);
        }
        uint32_t stA = (uint32_t)(ch & 1) * 20480;
        uint32_t stB = 40960 + (uint32_t)(ch & 1) * 10240;
#pragma unroll
        for (int ks = 0; ks < 2; ks++) {
            int kc = ks * 16;
            // A fragments: 2 m16 tiles for this warp's 32 rows
            uint32_t ah[2][4], al[2][4];
#pragma unroll
            for (int mt = 0; mt < 2; mt++) {
                int r = warp_m * 32 + mt * 16 + (lane & 15);
                uint32_t aoff = (uint32_t)(r * LDS + kc + ((lane >> 4) << 3)) * 2;
                ldm_x4(ah[mt], sb + stA + aoff);
                ldm_x4(al[mt], sb + stA + 10240 + aoff);
            }
            // B fragments: 3 n8 tiles for this warp's 24 cols
#pragma unroll
            for (int nt = 0; nt < 3; nt++) {
                int n = warp_n * 24 + nt * 8 + (lane & 7);
                uint32_t boff = (uint32_t)(n * LDS + kc + (((lane & 15) >> 3) << 3)) * 2;
                uint32_t bh[2], bl[2];
                ldm_x2(bh, sb + stB + boff);
                ldm_x2(bl, sb + stB + 5120 + boff);
#pragma unroll
                for (int mt = 0; mt < 2; mt++) {
                    mma_bf16(c[mt][nt], ah[mt], bh);
                    mma_bf16(c[mt][nt], al[mt], bh);
                    mma_bf16(c[mt][nt], ah[mt], bl);
                }
            }
        }
        if (ch + 1 < NCH) {
            int kn = (ch + 1) * 32;
            uint32_t nsA = (uint32_t)((ch + 1) & 1) * 20480;
            uint32_t nsB = 40960 + (uint32_t)((ch + 1) & 1) * 10240;
            float4 s = *(const float4*)&sBnA[kn + qa * 4];
            float4 h = *(const float4*)&sBnC[kn + qa * 4];
#pragma unroll
            for (int it = 0; it < 4; it++) {
                float4 v;
                v.x = fmaxf(fmaf(ra[it].x, s.x, h.x), 0.f);
                v.y = fmaxf(fmaf(ra[it].y, s.y, h.y), 0.f);
                v.z = fmaxf(fmaf(ra[it].z, s.z, h.z), 0.f);
                v.w = fmaxf(fmaf(ra[it].w, s.w, h.w), 0.f);
                if (!vA[it]) v = make_float4(0, 0, 0, 0);
                uint32_t h01, l01, h23, l23;
                split_pack(v.x, v.y, h01, l01);
                split_pack(v.z, v.w, h23, l23);
                *(uint2*)(smem + nsA + (rA[it] * LDS + qa * 4) * 2) = make_uint2(h01, h23);
                *(uint2*)(smem + nsA + 10240 + (rA[it] * LDS + qa * 4) * 2) = make_uint2(l01, l23);
            }
            *(uint4*)(smem + nsB + (nb * LDS + qb * 8) * 2) = rbh;
            *(uint4*)(smem + nsB + 5120 + (nb * LDS + qb * 8) * 2) = rbl;
        }
    }

    int colbase = warp_n * 24 + ((lane & 3) << 1);
    int rbase = row0 + warp_m * 32 + (lane >> 2);
#pragma unroll
    for (int mt = 0; mt < 2; mt++) {
        int r0g = rbase + mt * 16;
#pragma unroll
        for (int nt = 0; nt < 3; nt++) {
            int col = colbase + nt * 8;
            if (col >= CC) continue;
            float bx = bias[col], by = bias[col + 1];
            if (r0g < NN)
                *(float2*)(out + (size_t)r0g * CC + col) =
                    make_float2(c[mt][nt][0] + bx, c[mt][nt][1] + by);
            if (r0g + 8 < NN)
                *(float2*)(out + (size_t)(r0g + 8) * CC + col) =
                    make_float2(c[mt][nt][2] + bx, c[mt][nt][3] + by);
        }
    }
}

// ---------------- launch ----------------
extern "C" void kernel_launch(void* const* d_in, const int* in_sizes, int n_in,
                              void* d_out, int out_size) {
    const float* feat = (const float*)d_in[0];
    const int*   src  = (const int*)d_in[1];
    const int*   dst  = (const int*)d_in[2];
    const float* W1   = (const float*)d_in[3];
    const float* g1   = (const float*)d_in[5];
    const float* be1  = (const float*)d_in[6];
    const float* W2   = (const float*)d_in[7];
    const float* g2   = (const float*)d_in[9];
    const float* be2  = (const float*)d_in[10];
    const float* W3   = (const float*)d_in[11];
    const float* b3   = (const float*)d_in[12];
    float* out = (float*)d_out;

    float *p_z1, *p_z2, *p_z3, *p_z4, *p_y1, *p_y2, *p_stats;
    __nv_bfloat16 *p_w1h, *p_w1l, *p_w2h, *p_w2l, *p_w3h, *p_w3l;
    cudaGetSymbolAddress((void**)&p_z1, g_z1);
    cudaGetSymbolAddress((void**)&p_z2, g_z2);
    cudaGetSymbolAddress((void**)&p_z3, g_z3);
    cudaGetSymbolAddress((void**)&p_z4, g_z4);
    cudaGetSymbolAddress((void**)&p_y1, g_y1);
    cudaGetSymbolAddress((void**)&p_y2, g_y2);
    cudaGetSymbolAddress((void**)&p_stats, g_stats);
    cudaGetSymbolAddress((void**)&p_w1h, g_w1h);
    cudaGetSymbolAddress((void**)&p_w1l, g_w1l);
    cudaGetSymbolAddress((void**)&p_w2h, g_w2h);
    cudaGetSymbolAddress((void**)&p_w2l, g_w2l);
    cudaGetSymbolAddress((void**)&p_w3h, g_w3h);
    cudaGetSymbolAddress((void**)&p_w3l, g_w3l);

    const int SM1 = 61440;
    const int SM2 = 124928;
    const int SM3 = 63488;
    cudaFuncSetAttribute((const void*)k_mma1,
                         cudaFuncAttributeMaxDynamicSharedMemorySize, SM1);
    cudaFuncSetAttribute((const void*)k_mma2,
                         cudaFuncAttributeMaxDynamicSharedMemorySize, SM2);
    cudaFuncSetAttribute((const void*)k_mma3,
                         cudaFuncAttributeMaxDynamicSharedMemorySize, SM3);

    // CSR build (weight split fused into count)
    k_count<<<(EE + 255) / 256, 256>>>(dst, W1, W2, W3);
    k_scan1<<<NB_SCAN, 1024>>>();
    k_scan3<<<NB_SCAN, 1024>>>();
    k_fill<<<(EE + 255) / 256, 256>>>(src, dst);

    // propagation
    int gblocks = (NN * 32 + 255) / 256;
    k_gather<1><<<gblocks, 256>>>(feat, p_z1);
    k_gather<0><<<gblocks, 256>>>(p_z1, p_z2);
    k_gather<0><<<gblocks, 256>>>(p_z2, p_z3);
    k_gather<0><<<gblocks, 256>>>(p_z3, p_z4);

    int mgrid = (NN + 127) / 128;
    k_mma1<<<mgrid, 512, SM1>>>(p_z1, p_z2, p_z3, p_z4, feat,
                                p_w1h, p_w1l, p_y1, p_stats);
    k_mma2<<<mgrid, 512, SM2>>>(p_y1, p_w2h, p_w2l,
                                p_stats, g1, be1, p_y2, p_stats + 2 * HH);
    k_mma3<<<mgrid, 256, SM3>>>(p_y2, p_w3h, p_w3l,
                                p_stats + 2 * HH, g2, be2, b3, out);
}